// round 5
// baseline (speedup 1.0000x reference)
#include <cuda_runtime.h>

typedef unsigned long long ull;
#define BSZ 2
#define NN 50000
#define NEg 400000
#define TPB 256

__device__ float g_Pmsg[BSZ * NN * 128];
__device__ float g_Pupd[BSZ * NN * 128];
__device__ float g_Pn[BSZ * NN * 64];
__device__ float g_agg[BSZ * NN * 128];
__device__ float g_den[BSZ * NN];
__device__ float4 g_Wf4[256];   // fused W2@Wa1 as [c][j], float4 over j
__device__ float g_bf[16];      // b2@Wa1 + ba1

__device__ __forceinline__ ull fma2(ull a, ull b, ull c) {
    ull d; asm("fma.rn.f32x2 %0, %1, %2, %3;" : "=l"(d) : "l"(a), "l"(b), "l"(c)); return d;
}
__device__ __forceinline__ ull add2(ull a, ull b) {
    ull d; asm("add.rn.f32x2 %0, %1, %2;" : "=l"(d) : "l"(a), "l"(b)); return d;
}
__device__ __forceinline__ ull mul2(ull a, ull b) {
    ull d; asm("mul.rn.f32x2 %0, %1, %2;" : "=l"(d) : "l"(a), "l"(b)); return d;
}
__device__ __forceinline__ ull pk2(float x, float y) {
    ull r; asm("mov.b64 %0, {%1, %2};" : "=l"(r) : "f"(x), "f"(y)); return r;
}
__device__ __forceinline__ ull dup2(float x) {
    ull r; asm("mov.b64 %0, {%1, %1};" : "=l"(r) : "f"(x)); return r;
}
__device__ __forceinline__ float2 up2(ull v) {
    float2 r; asm("mov.b64 {%0, %1}, %2;" : "=f"(r.x), "=f"(r.y) : "l"(v)); return r;
}
__device__ __forceinline__ float silu_f(float x) { return x / (1.f + __expf(-x)); }
__device__ __forceinline__ void red4(float* p, float a, float b, float c, float d) {
    asm volatile("red.global.add.v4.f32 [%0], {%1,%2,%3,%4};"
                 :: "l"(p), "f"(a), "f"(b), "f"(c), "f"(d) : "memory");
}

__global__ void k_init() {
    float4 z = make_float4(0.f, 0.f, 0.f, 0.f);
    for (int i = blockIdx.x * blockDim.x + threadIdx.x; i < BSZ * NN * 32; i += gridDim.x * blockDim.x)
        ((float4*)g_agg)[i] = z;
    for (int i = blockIdx.x * blockDim.x + threadIdx.x; i < BSZ * NN; i += gridDim.x * blockDim.x)
        g_den[i] = 0.f;
}

// Wf[c][j] = sum_d W2[c][d]*Wa1[d][j];  bf[j] = b2@Wa1 + ba1
__global__ void k_fuse(const float* __restrict__ W2, const float* __restrict__ b2,
                       const float* __restrict__ Wa1, const float* __restrict__ ba1) {
    int idx = blockIdx.x * blockDim.x + threadIdx.x;
    if (idx < 1024) {
        int c = idx >> 4, j = idx & 15;
        float s = 0.f;
        for (int d = 0; d < 128; d++) s += W2[c * 128 + d] * Wa1[d * 16 + j];
        ((float*)g_Wf4)[c * 16 + j] = s;
    }
    if (idx < 16) {
        float s = ba1[idx];
        for (int d = 0; d < 128; d++) s += b2[d] * Wa1[d * 16 + idx];
        g_bf[idx] = s;
    }
}

// generic node precompute: out[n] (64 wide, as 32 ull per row) = V[n] @ W128 (128x64 block)
// P row stride and column offset in ull units.
__global__ void __launch_bounds__(TPB, 4)
k_pre(const float* __restrict__ V, const float* __restrict__ W,
      float* __restrict__ P, int rowStrideUll, int colOffUll) {
    __shared__ ull sW[128 * 32];   // 32 KB: sW[k*32+l] = (W[k][l], W[k][l+32])
    for (int i = threadIdx.x; i < 128 * 32; i += TPB) {
        int k = i >> 5, l = i & 31;
        sW[i] = pk2(W[k * 64 + l], W[k * 64 + l + 32]);
    }
    __syncthreads();
    const int warp = threadIdx.x >> 5, l = threadIdx.x & 31;
    const int nchunks = (BSZ * NN) / 8;
    for (int w = blockIdx.x * 8 + warp; w < nchunks; w += gridDim.x * 8) {
        const int r0 = w * 8;
        ull acc[8] = {0ULL, 0ULL, 0ULL, 0ULL, 0ULL, 0ULL, 0ULL, 0ULL};
        const float4* Vf = (const float4*)V + (size_t)r0 * 32;
#pragma unroll 4
        for (int k4 = 0; k4 < 32; k4++) {
            ull wk[4];
#pragma unroll
            for (int ki = 0; ki < 4; ki++) wk[ki] = sW[(k4 * 4 + ki) * 32 + l];
#pragma unroll
            for (int e = 0; e < 8; e++) {
                float4 v = __ldcs(Vf + e * 32 + k4);
                acc[e] = fma2(dup2(v.x), wk[0], acc[e]);
                acc[e] = fma2(dup2(v.y), wk[1], acc[e]);
                acc[e] = fma2(dup2(v.z), wk[2], acc[e]);
                acc[e] = fma2(dup2(v.w), wk[3], acc[e]);
            }
        }
        ull* Pu = (ull*)P;
#pragma unroll
        for (int e = 0; e < 8; e++)
            Pu[(size_t)(r0 + e) * rowStrideUll + colOffUll + l] = acc[e];
    }
}

// fused edge MLP, 8 edges/warp. MSG: attention + scatter; else write edge_delta.
// smem: sW1 (32KB) + Wf/bf/wa2 (~1.1KB) + sH (18KB) = 55424 B -> 4 CTAs/SM.
template <bool MSG>
__global__ void __launch_bounds__(TPB, 4)
k_edge(const float* __restrict__ E, const int* __restrict__ edges,
       const float* __restrict__ W1, const float* __restrict__ b1,
       const float* __restrict__ W2, const float* __restrict__ b2,
       const float* __restrict__ Wa2, const float* __restrict__ ba2,
       const float* __restrict__ P, float* __restrict__ outE) {
    extern __shared__ float sm[];
    ull*    sW1u = (ull*)sm;                 // floats 0..8192
    float4* sW1f = (float4*)sm;
    float4* sWfF = (float4*)(sm + 8192);     // 256 float4 -> floats 8192..9216
    float*  sBf  = sm + 9216;                // 16
    float*  sWa2s= sm + 9232;                // 16
    float*  sH   = sm + 9248;                // 8 warps * 576 = 4608 -> total 13856 floats

    for (int i = threadIdx.x; i < 128 * 32; i += TPB) {
        int k = i >> 5, l = i & 31;
        sW1u[(k >> 1) * 64 + l * 2 + (k & 1)] =
            pk2(W1[(256 + k) * 64 + l], W1[(256 + k) * 64 + l + 32]);
    }
    if (MSG) {
        for (int i = threadIdx.x; i < 256; i += TPB) sWfF[i] = g_Wf4[i];
        if (threadIdx.x < 16) { sBf[threadIdx.x] = g_bf[threadIdx.x]; sWa2s[threadIdx.x] = __ldg(Wa2 + threadIdx.x); }
    }
    const int warp = threadIdx.x >> 5, l = threadIdx.x & 31;
    const ull bbu  = pk2(__ldg(b1 + l), __ldg(b1 + l + 32));
    const ull b2lo = pk2(__ldg(b2 + 4 * l), __ldg(b2 + 4 * l + 1));
    const ull b2hi = pk2(__ldg(b2 + 4 * l + 2), __ldg(b2 + 4 * l + 3));
    const float ba2v = MSG ? __ldg(ba2) : 0.f;
    const float4* W2f = (const float4*)W2;   // [c][4l..4l+3] at c*32+l (L1-hot)
    __syncthreads();

    float* sHw = sH + warp * 576;   // 8 rows * 72
    const int nchunks = (BSZ * NEg) / 8;
    const int gw0 = blockIdx.x * 8 + warp;
    const int gstride = gridDim.x * 8;
    for (int w = gw0; w < nchunks; w += gstride) {
        const int ge0 = w * 8;
        const int b = ge0 / NEg;
        int sx[8], rx[8];
        const int2* edp = (const int2*)edges + ge0;
#pragma unroll
        for (int e = 0; e < 8; e++) { int2 t2 = __ldg(edp + e); sx[e] = t2.x; rx[e] = t2.y; }
        const ull* Pu = (const ull*)P + (size_t)b * NN * 64;
        ull h[8];
#pragma unroll
        for (int e = 0; e < 8; e++) {
            ull sp = __ldg(Pu + (size_t)sx[e] * 64 + l);
            ull rp = __ldg(Pu + (size_t)rx[e] * 64 + 32 + l);
            h[e] = add2(add2(sp, rp), bbu);
        }
        const float4* Ef = (const float4*)E + (size_t)ge0 * 32;
#pragma unroll 4
        for (int k4 = 0; k4 < 32; k4++) {
            float4 wa = sW1f[(2 * k4) * 32 + l];
            float4 wb = sW1f[(2 * k4 + 1) * 32 + l];
            ull w0 = pk2(wa.x, wa.y), w1 = pk2(wa.z, wa.w);
            ull w2_ = pk2(wb.x, wb.y), w3 = pk2(wb.z, wb.w);
#pragma unroll
            for (int e = 0; e < 8; e++) {
                float4 ev = __ldcs(Ef + e * 32 + k4);
                h[e] = fma2(dup2(ev.x), w0, h[e]);
                h[e] = fma2(dup2(ev.y), w1, h[e]);
                h[e] = fma2(dup2(ev.z), w2_, h[e]);
                h[e] = fma2(dup2(ev.w), w3, h[e]);
            }
        }
        __syncwarp();
#pragma unroll
        for (int e = 0; e < 8; e++) {
            float2 hh = up2(h[e]);
            sHw[e * 72 + l] = silu_f(hh.x);
            sHw[e * 72 + l + 32] = silu_f(hh.y);
        }
        __syncwarp();
        float ex[8]; float exf = 0.f;
        if (MSG) {
            const int e_att = l & 7, jg = l >> 3;
            const float* shrow = sHw + e_att * 72;
            float p0 = 0.f, p1 = 0.f, p2 = 0.f, p3 = 0.f;
#pragma unroll 8
            for (int c = 0; c < 64; c++) {
                float shc = shrow[c];
                float4 wfv = sWfF[c * 4 + jg];
                p0 += shc * wfv.x; p1 += shc * wfv.y;
                p2 += shc * wfv.z; p3 += shc * wfv.w;
            }
            float s = silu_f(p0 + sBf[jg * 4 + 0]) * sWa2s[jg * 4 + 0]
                    + silu_f(p1 + sBf[jg * 4 + 1]) * sWa2s[jg * 4 + 1]
                    + silu_f(p2 + sBf[jg * 4 + 2]) * sWa2s[jg * 4 + 2]
                    + silu_f(p3 + sBf[jg * 4 + 3]) * sWa2s[jg * 4 + 3];
            s += __shfl_xor_sync(0xffffffffu, s, 8);
            s += __shfl_xor_sync(0xffffffffu, s, 16);
            float logit = fminf(30.f, fmaxf(-30.f, ba2v + s));
            exf = __expf(logit);
#pragma unroll
            for (int e = 0; e < 8; e++) ex[e] = __shfl_sync(0xffffffffu, exf, e);
        }
        ull ma[8], mb[8];
#pragma unroll
        for (int e = 0; e < 8; e++) { ma[e] = b2lo; mb[e] = b2hi; }
#pragma unroll 2
        for (int c4 = 0; c4 < 16; c4++) {
            float4 hh[8];
#pragma unroll
            for (int e = 0; e < 8; e++) hh[e] = *(const float4*)(sHw + e * 72 + 4 * c4);
#pragma unroll
            for (int ci = 0; ci < 4; ci++) {
                int c = 4 * c4 + ci;
                float4 wv = __ldg(W2f + c * 32 + l);
                ull wlo = pk2(wv.x, wv.y), whi = pk2(wv.z, wv.w);
#pragma unroll
                for (int e = 0; e < 8; e++) {
                    float hv = (ci == 0) ? hh[e].x : (ci == 1) ? hh[e].y : (ci == 2) ? hh[e].z : hh[e].w;
                    ull d = dup2(hv);
                    ma[e] = fma2(d, wlo, ma[e]);
                    mb[e] = fma2(d, whi, mb[e]);
                }
            }
        }
        if (MSG) {
#pragma unroll
            for (int e = 0; e < 8; e++) {
                ull exd = dup2(ex[e]);
                float2 MA = up2(mul2(ma[e], exd)), MB = up2(mul2(mb[e], exd));
                float* ap = g_agg + (size_t)(b * NN + rx[e]) * 128 + 4 * l;
                red4(ap, MA.x, MA.y, MB.x, MB.y);
            }
            if (l < 8) {
                int2 t2 = __ldg(edp + l);
                atomicAdd(&g_den[b * NN + t2.y], exf);
            }
        } else {
#pragma unroll
            for (int e = 0; e < 8; e++) {
                float2 MA = up2(ma[e]), MB = up2(mb[e]);
                __stcs((float4*)outE + (size_t)(ge0 + e) * 32 + l,
                       make_float4(MA.x, MA.y, MB.x, MB.y));
            }
        }
        __syncwarp();
    }
}

// node output MLP: h = Pn[n] + bn1 + inv_den*(agg[n] @ Wn1_bot); silu; @ Wn2 + bn2
// smem: sW1 32KB + sH 18KB = 51200 B -> 4 CTAs/SM.
__global__ void __launch_bounds__(TPB, 4)
k_nodeout(const float* __restrict__ Wb, const float* __restrict__ bn1,
          const float* __restrict__ Wn2, const float* __restrict__ bn2,
          float* __restrict__ outN) {
    extern __shared__ float sm[];
    ull*    sW1u = (ull*)sm;                 // floats 0..8192
    float4* sW1f = (float4*)sm;
    float*  sH   = sm + 8192;                // 4608 -> total 12800 floats
    for (int i = threadIdx.x; i < 128 * 32; i += TPB) {
        int k = i >> 5, l = i & 31;
        sW1u[(k >> 1) * 64 + l * 2 + (k & 1)] =
            pk2(Wb[k * 64 + l], Wb[k * 64 + l + 32]);
    }
    const int warp = threadIdx.x >> 5, l = threadIdx.x & 31;
    const ull bbu  = pk2(__ldg(bn1 + l), __ldg(bn1 + l + 32));
    const ull b2lo = pk2(__ldg(bn2 + 4 * l), __ldg(bn2 + 4 * l + 1));
    const ull b2hi = pk2(__ldg(bn2 + 4 * l + 2), __ldg(bn2 + 4 * l + 3));
    const float4* W2f = (const float4*)Wn2;
    __syncthreads();

    float* sHw = sH + warp * 576;
    const int nchunks = (BSZ * NN) / 8;
    for (int w = blockIdx.x * 8 + warp; w < nchunks; w += gridDim.x * 8) {
        const int r0 = w * 8;
        float inv[8];
#pragma unroll
        for (int e = 0; e < 8; e++) {
            float d = __ldg(g_den + r0 + e);
            inv[e] = d != 0.f ? 1.f / d : 0.f;
        }
        ull h[8] = {0ULL, 0ULL, 0ULL, 0ULL, 0ULL, 0ULL, 0ULL, 0ULL};
        const float4* Af = (const float4*)g_agg + (size_t)r0 * 32;
#pragma unroll 4
        for (int k4 = 0; k4 < 32; k4++) {
            float4 wa = sW1f[(2 * k4) * 32 + l];
            float4 wb = sW1f[(2 * k4 + 1) * 32 + l];
            ull w0 = pk2(wa.x, wa.y), w1 = pk2(wa.z, wa.w);
            ull w2_ = pk2(wb.x, wb.y), w3 = pk2(wb.z, wb.w);
#pragma unroll
            for (int e = 0; e < 8; e++) {
                float4 ev = __ldcs(Af + e * 32 + k4);
                h[e] = fma2(dup2(ev.x), w0, h[e]);
                h[e] = fma2(dup2(ev.y), w1, h[e]);
                h[e] = fma2(dup2(ev.z), w2_, h[e]);
                h[e] = fma2(dup2(ev.w), w3, h[e]);
            }
        }
        const ull* Pnu = (const ull*)g_Pn;
        __syncwarp();
#pragma unroll
        for (int e = 0; e < 8; e++) {
            ull base = add2(__ldg(Pnu + (size_t)(r0 + e) * 32 + l), bbu);
            float2 hh = up2(fma2(dup2(inv[e]), h[e], base));
            sHw[e * 72 + l] = silu_f(hh.x);
            sHw[e * 72 + l + 32] = silu_f(hh.y);
        }
        __syncwarp();
        ull ma[8], mb[8];
#pragma unroll
        for (int e = 0; e < 8; e++) { ma[e] = b2lo; mb[e] = b2hi; }
#pragma unroll 2
        for (int c4 = 0; c4 < 16; c4++) {
            float4 hh[8];
#pragma unroll
            for (int e = 0; e < 8; e++) hh[e] = *(const float4*)(sHw + e * 72 + 4 * c4);
#pragma unroll
            for (int ci = 0; ci < 4; ci++) {
                int c = 4 * c4 + ci;
                float4 wv = __ldg(W2f + c * 32 + l);
                ull wlo = pk2(wv.x, wv.y), whi = pk2(wv.z, wv.w);
#pragma unroll
                for (int e = 0; e < 8; e++) {
                    float hv = (ci == 0) ? hh[e].x : (ci == 1) ? hh[e].y : (ci == 2) ? hh[e].z : hh[e].w;
                    ull d = dup2(hv);
                    ma[e] = fma2(d, wlo, ma[e]);
                    mb[e] = fma2(d, whi, mb[e]);
                }
            }
        }
#pragma unroll
        for (int e = 0; e < 8; e++) {
            float2 MA = up2(ma[e]), MB = up2(mb[e]);
            __stcs((float4*)outN + (size_t)(r0 + e) * 32 + l,
                   make_float4(MA.x, MA.y, MB.x, MB.y));
        }
        __syncwarp();
    }
}

extern "C" void kernel_launch(void* const* d_in, const int* in_sizes, int n_in,
                              void* d_out, int out_size) {
    const float* V = (const float*)d_in[0];
    const float* E = (const float*)d_in[1];
    const int* edges = (const int*)d_in[2];
    const float* Wm1 = (const float*)d_in[3];
    const float* bm1 = (const float*)d_in[4];
    const float* Wm2 = (const float*)d_in[5];
    const float* bm2 = (const float*)d_in[6];
    const float* Wa1 = (const float*)d_in[7];
    const float* ba1 = (const float*)d_in[8];
    const float* Wa2 = (const float*)d_in[9];
    const float* ba2 = (const float*)d_in[10];
    const float* Wu1 = (const float*)d_in[11];
    const float* bu1 = (const float*)d_in[12];
    const float* Wu2 = (const float*)d_in[13];
    const float* bu2 = (const float*)d_in[14];
    const float* Wn1 = (const float*)d_in[15];
    const float* bn1 = (const float*)d_in[16];
    const float* Wn2 = (const float*)d_in[17];
    const float* bn2 = (const float*)d_in[18];
    float* outN = (float*)d_out;
    float* outE = outN + (size_t)BSZ * NN * 128;

    float* Pmsg; cudaGetSymbolAddress((void**)&Pmsg, g_Pmsg);
    float* Pupd; cudaGetSymbolAddress((void**)&Pupd, g_Pupd);
    float* Pn;   cudaGetSymbolAddress((void**)&Pn, g_Pn);

    cudaFuncSetAttribute(k_edge<true>, cudaFuncAttributeMaxDynamicSharedMemorySize, 55424);
    cudaFuncSetAttribute(k_edge<false>, cudaFuncAttributeMaxDynamicSharedMemorySize, 55424);
    cudaFuncSetAttribute(k_nodeout, cudaFuncAttributeMaxDynamicSharedMemorySize, 51200);

    k_init<<<592, TPB>>>();
    k_fuse<<<8, TPB>>>(Wm2, bm2, Wa1, ba1);
    k_pre<<<592, TPB>>>(V, Wm1,            Pmsg, 64, 0);
    k_pre<<<592, TPB>>>(V, Wm1 + 128 * 64, Pmsg, 64, 32);
    k_pre<<<592, TPB>>>(V, Wu1,            Pupd, 64, 0);
    k_pre<<<592, TPB>>>(V, Wu1 + 128 * 64, Pupd, 64, 32);
    k_pre<<<592, TPB>>>(V, Wn1,            Pn,   32, 0);
    k_edge<true><<<592, TPB, 55424>>>(E, edges, Wm1, bm1, Wm2, bm2, Wa2, ba2, Pmsg, nullptr);
    k_edge<false><<<592, TPB, 55424>>>(E, edges, Wu1, bu1, Wu2, bu2, nullptr, nullptr, Pupd, outE);
    k_nodeout<<<592, TPB, 51200>>>(Wn1 + 128 * 64, bn1, Wn2, bn2, outN);
}

// round 6
// speedup vs baseline: 1.3749x; 1.3749x over previous
#include <cuda_runtime.h>

typedef unsigned long long ull;
#define BSZ 2
#define NN 50000
#define NEg 400000
#define TPB 256

__device__ float g_Pmsg[BSZ * NN * 128];
__device__ float g_Pupd[BSZ * NN * 128];
__device__ float g_Pn[BSZ * NN * 64];
__device__ float g_agg[BSZ * NN * 128];
__device__ float g_den[BSZ * NN];
__device__ float4 g_Wf4[256];   // fused W2@Wa1 as [c][j], float4 over j
__device__ float g_bf[16];      // b2@Wa1 + ba1

__device__ __forceinline__ ull fma2(ull a, ull b, ull c) {
    ull d; asm("fma.rn.f32x2 %0, %1, %2, %3;" : "=l"(d) : "l"(a), "l"(b), "l"(c)); return d;
}
__device__ __forceinline__ ull add2(ull a, ull b) {
    ull d; asm("add.rn.f32x2 %0, %1, %2;" : "=l"(d) : "l"(a), "l"(b)); return d;
}
__device__ __forceinline__ ull mul2(ull a, ull b) {
    ull d; asm("mul.rn.f32x2 %0, %1, %2;" : "=l"(d) : "l"(a), "l"(b)); return d;
}
__device__ __forceinline__ ull pk2(float x, float y) {
    ull r; asm("mov.b64 %0, {%1, %2};" : "=l"(r) : "f"(x), "f"(y)); return r;
}
__device__ __forceinline__ ull dup2(float x) {
    ull r; asm("mov.b64 %0, {%1, %1};" : "=l"(r) : "f"(x)); return r;
}
__device__ __forceinline__ float2 up2(ull v) {
    float2 r; asm("mov.b64 {%0, %1}, %2;" : "=f"(r.x), "=f"(r.y) : "l"(v)); return r;
}
__device__ __forceinline__ float silu_f(float x) { return x / (1.f + __expf(-x)); }
__device__ __forceinline__ void red4(float* p, float a, float b, float c, float d) {
    asm volatile("red.global.add.v4.f32 [%0], {%1,%2,%3,%4};"
                 :: "l"(p), "f"(a), "f"(b), "f"(c), "f"(d) : "memory");
}

__global__ void k_init() {
    float4 z = make_float4(0.f, 0.f, 0.f, 0.f);
    for (int i = blockIdx.x * blockDim.x + threadIdx.x; i < BSZ * NN * 32; i += gridDim.x * blockDim.x)
        ((float4*)g_agg)[i] = z;
    for (int i = blockIdx.x * blockDim.x + threadIdx.x; i < BSZ * NN; i += gridDim.x * blockDim.x)
        g_den[i] = 0.f;
}

// Wf[c][j] = sum_d W2[c][d]*Wa1[d][j];  bf[j] = b2@Wa1 + ba1
__global__ void k_fuse(const float* __restrict__ W2, const float* __restrict__ b2,
                       const float* __restrict__ Wa1, const float* __restrict__ ba1) {
    int idx = blockIdx.x * blockDim.x + threadIdx.x;
    if (idx < 1024) {
        int c = idx >> 4, j = idx & 15;
        float s = 0.f;
        for (int d = 0; d < 128; d++) s += W2[c * 128 + d] * Wa1[d * 16 + j];
        ((float*)g_Wf4)[c * 16 + j] = s;
    }
    if (idx < 16) {
        float s = ba1[idx];
        for (int d = 0; d < 128; d++) s += b2[d] * Wa1[d * 16 + idx];
        g_bf[idx] = s;
    }
}

// full-width node precompute (round-4 style): P row (ull): [0..31]=sender pairs, [32..63]=receiver pairs
__global__ void k_node_pre(const float* __restrict__ V, const float* __restrict__ Wg, float* __restrict__ P) {
    extern __shared__ float sm[];
    float4* sW = (float4*)sm;           // 4096 float4 (64KB)
    float* sV = sm + 16384;             // 32*128 = 4096 floats (16KB)
    for (int i = threadIdx.x; i < 128 * 32; i += TPB) {
        int k = i >> 5, l = i & 31;
        sW[i] = make_float4(Wg[k * 64 + l], Wg[k * 64 + l + 32],
                            Wg[(128 + k) * 64 + l], Wg[(128 + k) * 64 + l + 32]);
    }
    __syncthreads();
    const ull* sWu = (const ull*)sW;
    const int warp = threadIdx.x >> 5, l = threadIdx.x & 31;
    const int ntiles = (BSZ * NN) / 32;
    for (int t = blockIdx.x; t < ntiles; t += gridDim.x) {
        __syncthreads();
        const float4* Vg = (const float4*)V + (size_t)t * 32 * 32;
        for (int i = threadIdx.x; i < 32 * 32; i += TPB) ((float4*)sV)[i] = __ldcs(Vg + i);
        __syncthreads();
        const int r0 = 4 * warp;
        ull a[4] = {0ULL, 0ULL, 0ULL, 0ULL}, bq[4] = {0ULL, 0ULL, 0ULL, 0ULL};
        const float4* sV4 = (const float4*)sV;
#pragma unroll 4
        for (int k4 = 0; k4 < 32; k4++) {
            ull wa[4], wb[4];
#pragma unroll
            for (int ki = 0; ki < 4; ki++) {
                int k = k4 * 4 + ki;
                wa[ki] = sWu[(k * 32 + l) * 2];
                wb[ki] = sWu[(k * 32 + l) * 2 + 1];
            }
#pragma unroll
            for (int r = 0; r < 4; r++) {
                float4 v = sV4[(r0 + r) * 32 + k4];
                a[r] = fma2(dup2(v.x), wa[0], a[r]); bq[r] = fma2(dup2(v.x), wb[0], bq[r]);
                a[r] = fma2(dup2(v.y), wa[1], a[r]); bq[r] = fma2(dup2(v.y), wb[1], bq[r]);
                a[r] = fma2(dup2(v.z), wa[2], a[r]); bq[r] = fma2(dup2(v.z), wb[2], bq[r]);
                a[r] = fma2(dup2(v.w), wa[3], a[r]); bq[r] = fma2(dup2(v.w), wb[3], bq[r]);
            }
        }
#pragma unroll
        for (int r = 0; r < 4; r++) {
            ull* p = (ull*)(P + ((size_t)t * 32 + r0 + r) * 128);
            p[l] = a[r]; p[32 + l] = bq[r];
        }
    }
}

// half-width precompute (for Pn): out[n] (32 ull) = V[n] @ W (128x64)
__global__ void __launch_bounds__(TPB, 4)
k_pre(const float* __restrict__ V, const float* __restrict__ W,
      float* __restrict__ P, int rowStrideUll, int colOffUll) {
    __shared__ ull sW[128 * 32];
    for (int i = threadIdx.x; i < 128 * 32; i += TPB) {
        int k = i >> 5, l = i & 31;
        sW[i] = pk2(W[k * 64 + l], W[k * 64 + l + 32]);
    }
    __syncthreads();
    const int warp = threadIdx.x >> 5, l = threadIdx.x & 31;
    const int nchunks = (BSZ * NN) / 8;
    for (int w = blockIdx.x * 8 + warp; w < nchunks; w += gridDim.x * 8) {
        const int r0 = w * 8;
        ull acc[8] = {0ULL, 0ULL, 0ULL, 0ULL, 0ULL, 0ULL, 0ULL, 0ULL};
        const float4* Vf = (const float4*)V + (size_t)r0 * 32;
#pragma unroll 4
        for (int k4 = 0; k4 < 32; k4++) {
            ull wk[4];
#pragma unroll
            for (int ki = 0; ki < 4; ki++) wk[ki] = sW[(k4 * 4 + ki) * 32 + l];
#pragma unroll
            for (int e = 0; e < 8; e++) {
                float4 v = __ldcs(Vf + e * 32 + k4);
                acc[e] = fma2(dup2(v.x), wk[0], acc[e]);
                acc[e] = fma2(dup2(v.y), wk[1], acc[e]);
                acc[e] = fma2(dup2(v.z), wk[2], acc[e]);
                acc[e] = fma2(dup2(v.w), wk[3], acc[e]);
            }
        }
        ull* Pu = (ull*)P;
#pragma unroll
        for (int e = 0; e < 8; e++)
            Pu[(size_t)(r0 + e) * rowStrideUll + colOffUll + l] = acc[e];
    }
}

// fused edge MLP, 8 edges/warp, 64 edges/CTA-iter; E staged in smem (union with sH).
// smem floats: sW1 8192 | sW2 8192 | Wf 1024 | bf 16 | wa2 16 | union 8192 = 25632 fl = 102528 B
template <bool MSG>
__global__ void __launch_bounds__(TPB, 2)
k_edge(const float* __restrict__ E, const int* __restrict__ edges,
       const float* __restrict__ W1, const float* __restrict__ b1,
       const float* __restrict__ W2, const float* __restrict__ b2,
       const float* __restrict__ Wa2, const float* __restrict__ ba2,
       const float* __restrict__ P, float* __restrict__ outE) {
    extern __shared__ float sm[];
    ull*    sW1u = (ull*)sm;
    float4* sW1f = (float4*)sm;
    float4* sW2f = (float4*)(sm + 8192);
    float4* sWfF = (float4*)(sm + 16384);
    float*  sBf  = sm + 17408;
    float*  sWa2s= sm + 17424;
    float*  sU   = sm + 17440;    // 8192 floats: E tile (64 x 128) / per-warp sH

    for (int i = threadIdx.x; i < 128 * 32; i += TPB) {
        int k = i >> 5, l = i & 31;
        sW1u[(k >> 1) * 64 + l * 2 + (k & 1)] =
            pk2(W1[(256 + k) * 64 + l], W1[(256 + k) * 64 + l + 32]);
    }
    for (int i = threadIdx.x; i < 64 * 32; i += TPB) {
        int j = i >> 5, l = i & 31;
        sW2f[i] = make_float4(W2[j * 128 + 4 * l], W2[j * 128 + 4 * l + 1],
                              W2[j * 128 + 4 * l + 2], W2[j * 128 + 4 * l + 3]);
    }
    if (MSG) {
        for (int i = threadIdx.x; i < 256; i += TPB) sWfF[i] = g_Wf4[i];
        if (threadIdx.x < 16) { sBf[threadIdx.x] = g_bf[threadIdx.x]; sWa2s[threadIdx.x] = __ldg(Wa2 + threadIdx.x); }
    }
    const int warp = threadIdx.x >> 5, l = threadIdx.x & 31;
    const ull bbu  = pk2(__ldg(b1 + l), __ldg(b1 + l + 32));
    const ull b2lo = pk2(__ldg(b2 + 4 * l), __ldg(b2 + 4 * l + 1));
    const ull b2hi = pk2(__ldg(b2 + 4 * l + 2), __ldg(b2 + 4 * l + 3));
    const float ba2v = MSG ? __ldg(ba2) : 0.f;
    __syncthreads();

    float* sHw = sU + warp * 1024;   // inside this warp's own E-tile quarter
    const float4* sU4 = (const float4*)sU;
    const int ntiles = (BSZ * NEg) / 64;
    for (int t = blockIdx.x; t < ntiles; t += gridDim.x) {
        __syncthreads();
        const float4* Ef = (const float4*)E + (size_t)t * 64 * 32;
        for (int i = threadIdx.x; i < 64 * 32; i += TPB) ((float4*)sU)[i] = __ldcs(Ef + i);
        __syncthreads();
        const int ge0 = t * 64 + warp * 8;
        const int b = ge0 / NEg;
        int sx[8], rx[8];
        const int2* edp = (const int2*)edges + ge0;
#pragma unroll
        for (int e = 0; e < 8; e++) { int2 t2 = __ldg(edp + e); sx[e] = t2.x; rx[e] = t2.y; }
        const ull* Pu = (const ull*)P + (size_t)b * NN * 64;
        ull h[8];
#pragma unroll
        for (int e = 0; e < 8; e++) {
            ull sp = __ldg(Pu + (size_t)sx[e] * 64 + l);
            ull rp = __ldg(Pu + (size_t)rx[e] * 64 + 32 + l);
            h[e] = add2(add2(sp, rp), bbu);
        }
#pragma unroll 4
        for (int k4 = 0; k4 < 32; k4++) {
            float4 wa = sW1f[(2 * k4) * 32 + l];
            float4 wb = sW1f[(2 * k4 + 1) * 32 + l];
            ull w0 = pk2(wa.x, wa.y), w1 = pk2(wa.z, wa.w);
            ull w2_ = pk2(wb.x, wb.y), w3 = pk2(wb.z, wb.w);
#pragma unroll
            for (int e = 0; e < 8; e++) {
                float4 ev = sU4[(warp * 8 + e) * 32 + k4];
                h[e] = fma2(dup2(ev.x), w0, h[e]);
                h[e] = fma2(dup2(ev.y), w1, h[e]);
                h[e] = fma2(dup2(ev.z), w2_, h[e]);
                h[e] = fma2(dup2(ev.w), w3, h[e]);
            }
        }
        __syncwarp();
#pragma unroll
        for (int e = 0; e < 8; e++) {
            float2 hh = up2(h[e]);
            sHw[e * 72 + l] = silu_f(hh.x);
            sHw[e * 72 + l + 32] = silu_f(hh.y);
        }
        __syncwarp();
        float ex[8]; float exf = 0.f;
        if (MSG) {
            const int e_att = l & 7, jg = l >> 3;
            const float* shrow = sHw + e_att * 72;
            float p0 = 0.f, p1 = 0.f, p2 = 0.f, p3 = 0.f;
#pragma unroll 8
            for (int c = 0; c < 64; c++) {
                float shc = shrow[c];
                float4 wfv = sWfF[c * 4 + jg];
                p0 += shc * wfv.x; p1 += shc * wfv.y;
                p2 += shc * wfv.z; p3 += shc * wfv.w;
            }
            float s = silu_f(p0 + sBf[jg * 4 + 0]) * sWa2s[jg * 4 + 0]
                    + silu_f(p1 + sBf[jg * 4 + 1]) * sWa2s[jg * 4 + 1]
                    + silu_f(p2 + sBf[jg * 4 + 2]) * sWa2s[jg * 4 + 2]
                    + silu_f(p3 + sBf[jg * 4 + 3]) * sWa2s[jg * 4 + 3];
            s += __shfl_xor_sync(0xffffffffu, s, 8);
            s += __shfl_xor_sync(0xffffffffu, s, 16);
            float logit = fminf(30.f, fmaxf(-30.f, ba2v + s));
            exf = __expf(logit);
#pragma unroll
            for (int e = 0; e < 8; e++) ex[e] = __shfl_sync(0xffffffffu, exf, e);
        }
        ull ma[8], mb[8];
#pragma unroll
        for (int e = 0; e < 8; e++) { ma[e] = b2lo; mb[e] = b2hi; }
#pragma unroll 2
        for (int c4 = 0; c4 < 16; c4++) {
            float4 hh[8];
#pragma unroll
            for (int e = 0; e < 8; e++) hh[e] = *(const float4*)(sHw + e * 72 + 4 * c4);
#pragma unroll
            for (int ci = 0; ci < 4; ci++) {
                int c = 4 * c4 + ci;
                float4 wv = sW2f[c * 32 + l];
                ull wlo = pk2(wv.x, wv.y), whi = pk2(wv.z, wv.w);
#pragma unroll
                for (int e = 0; e < 8; e++) {
                    float hv = (ci == 0) ? hh[e].x : (ci == 1) ? hh[e].y : (ci == 2) ? hh[e].z : hh[e].w;
                    ull d = dup2(hv);
                    ma[e] = fma2(d, wlo, ma[e]);
                    mb[e] = fma2(d, whi, mb[e]);
                }
            }
        }
        if (MSG) {
#pragma unroll
            for (int e = 0; e < 8; e++) {
                ull exd = dup2(ex[e]);
                float2 MA = up2(mul2(ma[e], exd)), MB = up2(mul2(mb[e], exd));
                float* ap = g_agg + (size_t)(b * NN + rx[e]) * 128 + 4 * l;
                red4(ap, MA.x, MA.y, MB.x, MB.y);
            }
            if (l < 8) {
                int2 t2 = __ldg(edp + l);
                atomicAdd(&g_den[b * NN + t2.y], exf);
            }
        } else {
#pragma unroll
            for (int e = 0; e < 8; e++) {
                float2 MA = up2(ma[e]), MB = up2(mb[e]);
                __stcs((float4*)outE + (size_t)(ge0 + e) * 32 + l,
                       make_float4(MA.x, MA.y, MB.x, MB.y));
            }
        }
        __syncwarp();
    }
}

// node output MLP with Pn hoist; Wn1-bottom AND Wn2 both in smem.
// smem floats: sW1 8192 + sW2 8192 + sH 4608 = 20992 fl = 83968 B -> 2 CTAs/SM.
__global__ void __launch_bounds__(TPB, 2)
k_nodeout(const float* __restrict__ Wb, const float* __restrict__ bn1,
          const float* __restrict__ Wn2, const float* __restrict__ bn2,
          float* __restrict__ outN) {
    extern __shared__ float sm[];
    ull*    sW1u = (ull*)sm;
    float4* sW1f = (float4*)sm;
    float4* sW2f = (float4*)(sm + 8192);
    float*  sH   = sm + 16384;
    for (int i = threadIdx.x; i < 128 * 32; i += TPB) {
        int k = i >> 5, l = i & 31;
        sW1u[(k >> 1) * 64 + l * 2 + (k & 1)] =
            pk2(Wb[k * 64 + l], Wb[k * 64 + l + 32]);
    }
    for (int i = threadIdx.x; i < 64 * 32; i += TPB) {
        int j = i >> 5, l = i & 31;
        sW2f[i] = make_float4(Wn2[j * 128 + 4 * l], Wn2[j * 128 + 4 * l + 1],
                              Wn2[j * 128 + 4 * l + 2], Wn2[j * 128 + 4 * l + 3]);
    }
    const int warp = threadIdx.x >> 5, l = threadIdx.x & 31;
    const ull bbu  = pk2(__ldg(bn1 + l), __ldg(bn1 + l + 32));
    const ull b2lo = pk2(__ldg(bn2 + 4 * l), __ldg(bn2 + 4 * l + 1));
    const ull b2hi = pk2(__ldg(bn2 + 4 * l + 2), __ldg(bn2 + 4 * l + 3));
    __syncthreads();

    float* sHw = sH + warp * 576;
    const int nchunks = (BSZ * NN) / 8;
    for (int w = blockIdx.x * 8 + warp; w < nchunks; w += gridDim.x * 8) {
        const int r0 = w * 8;
        float inv[8];
#pragma unroll
        for (int e = 0; e < 8; e++) {
            float d = __ldg(g_den + r0 + e);
            inv[e] = d != 0.f ? 1.f / d : 0.f;
        }
        ull h[8] = {0ULL, 0ULL, 0ULL, 0ULL, 0ULL, 0ULL, 0ULL, 0ULL};
        const float4* Af = (const float4*)g_agg + (size_t)r0 * 32;
#pragma unroll 4
        for (int k4 = 0; k4 < 32; k4++) {
            float4 wa = sW1f[(2 * k4) * 32 + l];
            float4 wb = sW1f[(2 * k4 + 1) * 32 + l];
            ull w0 = pk2(wa.x, wa.y), w1 = pk2(wa.z, wa.w);
            ull w2_ = pk2(wb.x, wb.y), w3 = pk2(wb.z, wb.w);
#pragma unroll
            for (int e = 0; e < 8; e++) {
                float4 ev = __ldcs(Af + e * 32 + k4);
                h[e] = fma2(dup2(ev.x), w0, h[e]);
                h[e] = fma2(dup2(ev.y), w1, h[e]);
                h[e] = fma2(dup2(ev.z), w2_, h[e]);
                h[e] = fma2(dup2(ev.w), w3, h[e]);
            }
        }
        const ull* Pnu = (const ull*)g_Pn;
        __syncwarp();
#pragma unroll
        for (int e = 0; e < 8; e++) {
            ull base = add2(__ldg(Pnu + (size_t)(r0 + e) * 32 + l), bbu);
            float2 hh = up2(fma2(dup2(inv[e]), h[e], base));
            sHw[e * 72 + l] = silu_f(hh.x);
            sHw[e * 72 + l + 32] = silu_f(hh.y);
        }
        __syncwarp();
        ull ma[8], mb[8];
#pragma unroll
        for (int e = 0; e < 8; e++) { ma[e] = b2lo; mb[e] = b2hi; }
#pragma unroll 2
        for (int c4 = 0; c4 < 16; c4++) {
            float4 hh[8];
#pragma unroll
            for (int e = 0; e < 8; e++) hh[e] = *(const float4*)(sHw + e * 72 + 4 * c4);
#pragma unroll
            for (int ci = 0; ci < 4; ci++) {
                int c = 4 * c4 + ci;
                float4 wv = sW2f[c * 32 + l];
                ull wlo = pk2(wv.x, wv.y), whi = pk2(wv.z, wv.w);
#pragma unroll
                for (int e = 0; e < 8; e++) {
                    float hv = (ci == 0) ? hh[e].x : (ci == 1) ? hh[e].y : (ci == 2) ? hh[e].z : hh[e].w;
                    ull d = dup2(hv);
                    ma[e] = fma2(d, wlo, ma[e]);
                    mb[e] = fma2(d, whi, mb[e]);
                }
            }
        }
#pragma unroll
        for (int e = 0; e < 8; e++) {
            float2 MA = up2(ma[e]), MB = up2(mb[e]);
            __stcs((float4*)outN + (size_t)(r0 + e) * 32 + l,
                   make_float4(MA.x, MA.y, MB.x, MB.y));
        }
        __syncwarp();
    }
}

extern "C" void kernel_launch(void* const* d_in, const int* in_sizes, int n_in,
                              void* d_out, int out_size) {
    const float* V = (const float*)d_in[0];
    const float* E = (const float*)d_in[1];
    const int* edges = (const int*)d_in[2];
    const float* Wm1 = (const float*)d_in[3];
    const float* bm1 = (const float*)d_in[4];
    const float* Wm2 = (const float*)d_in[5];
    const float* bm2 = (const float*)d_in[6];
    const float* Wa1 = (const float*)d_in[7];
    const float* ba1 = (const float*)d_in[8];
    const float* Wa2 = (const float*)d_in[9];
    const float* ba2 = (const float*)d_in[10];
    const float* Wu1 = (const float*)d_in[11];
    const float* bu1 = (const float*)d_in[12];
    const float* Wu2 = (const float*)d_in[13];
    const float* bu2 = (const float*)d_in[14];
    const float* Wn1 = (const float*)d_in[15];
    const float* bn1 = (const float*)d_in[16];
    const float* Wn2 = (const float*)d_in[17];
    const float* bn2 = (const float*)d_in[18];
    float* outN = (float*)d_out;
    float* outE = outN + (size_t)BSZ * NN * 128;

    float* Pmsg; cudaGetSymbolAddress((void**)&Pmsg, g_Pmsg);
    float* Pupd; cudaGetSymbolAddress((void**)&Pupd, g_Pupd);
    float* Pn;   cudaGetSymbolAddress((void**)&Pn, g_Pn);

    cudaFuncSetAttribute(k_node_pre, cudaFuncAttributeMaxDynamicSharedMemorySize, 81920);
    cudaFuncSetAttribute(k_edge<true>, cudaFuncAttributeMaxDynamicSharedMemorySize, 102528);
    cudaFuncSetAttribute(k_edge<false>, cudaFuncAttributeMaxDynamicSharedMemorySize, 102528);
    cudaFuncSetAttribute(k_nodeout, cudaFuncAttributeMaxDynamicSharedMemorySize, 83968);

    k_init<<<592, TPB>>>();
    k_fuse<<<8, TPB>>>(Wm2, bm2, Wa1, ba1);
    k_node_pre<<<592, TPB, 81920>>>(V, Wm1, Pmsg);
    k_node_pre<<<592, TPB, 81920>>>(V, Wu1, Pupd);
    k_pre<<<592, TPB>>>(V, Wn1, Pn, 32, 0);
    k_edge<true><<<592, TPB, 102528>>>(E, edges, Wm1, bm1, Wm2, bm2, Wa2, ba2, Pmsg, nullptr);
    k_edge<false><<<592, TPB, 102528>>>(E, edges, Wu1, bu1, Wu2, bu2, nullptr, nullptr, Pupd, outE);
    k_nodeout<<<592, TPB, 83968>>>(Wn1 + 128 * 64, bn1, Wn2, bn2, outN);
}

// round 7
// speedup vs baseline: 1.4870x; 1.0815x over previous
#include <cuda_runtime.h>

typedef unsigned long long ull;
#define BSZ 2
#define NN 50000
#define NEg 400000
#define TPB 256

__device__ float g_Pmsg[BSZ * NN * 128];
__device__ float g_Pupd[BSZ * NN * 128];
__device__ float g_Pn[BSZ * NN * 64];
__device__ float g_agg[BSZ * NN * 128];
__device__ float g_den[BSZ * NN];
__device__ float4 g_Wf4[256];   // fused W2@Wa1 as [c][j], float4 over j
__device__ float g_bf[16];      // b2@Wa1 + ba1

__device__ __forceinline__ ull fma2(ull a, ull b, ull c) {
    ull d; asm("fma.rn.f32x2 %0, %1, %2, %3;" : "=l"(d) : "l"(a), "l"(b), "l"(c)); return d;
}
__device__ __forceinline__ ull add2(ull a, ull b) {
    ull d; asm("add.rn.f32x2 %0, %1, %2;" : "=l"(d) : "l"(a), "l"(b)); return d;
}
__device__ __forceinline__ ull mul2(ull a, ull b) {
    ull d; asm("mul.rn.f32x2 %0, %1, %2;" : "=l"(d) : "l"(a), "l"(b)); return d;
}
__device__ __forceinline__ ull pk2(float x, float y) {
    ull r; asm("mov.b64 %0, {%1, %2};" : "=l"(r) : "f"(x), "f"(y)); return r;
}
__device__ __forceinline__ ull dup2(float x) {
    ull r; asm("mov.b64 %0, {%1, %1};" : "=l"(r) : "f"(x)); return r;
}
__device__ __forceinline__ float2 up2(ull v) {
    float2 r; asm("mov.b64 {%0, %1}, %2;" : "=f"(r.x), "=f"(r.y) : "l"(v)); return r;
}
__device__ __forceinline__ float silu_f(float x) { return x / (1.f + __expf(-x)); }
__device__ __forceinline__ void red4(float* p, float a, float b, float c, float d) {
    asm volatile("red.global.add.v4.f32 [%0], {%1,%2,%3,%4};"
                 :: "l"(p), "f"(a), "f"(b), "f"(c), "f"(d) : "memory");
}

__global__ void k_init() {
    float4 z = make_float4(0.f, 0.f, 0.f, 0.f);
    for (int i = blockIdx.x * blockDim.x + threadIdx.x; i < BSZ * NN * 32; i += gridDim.x * blockDim.x)
        ((float4*)g_agg)[i] = z;
    for (int i = blockIdx.x * blockDim.x + threadIdx.x; i < BSZ * NN; i += gridDim.x * blockDim.x)
        g_den[i] = 0.f;
}

// Wf[c][j] = sum_d W2[c][d]*Wa1[d][j];  bf[j] = b2@Wa1 + ba1
__global__ void k_fuse(const float* __restrict__ W2, const float* __restrict__ b2,
                       const float* __restrict__ Wa1, const float* __restrict__ ba1) {
    int idx = blockIdx.x * blockDim.x + threadIdx.x;
    if (idx < 1024) {
        int c = idx >> 4, j = idx & 15;
        float s = 0.f;
        for (int d = 0; d < 128; d++) s += W2[c * 128 + d] * Wa1[d * 16 + j];
        ((float*)g_Wf4)[c * 16 + j] = s;
    }
    if (idx < 16) {
        float s = ba1[idx];
        for (int d = 0; d < 128; d++) s += b2[d] * Wa1[d * 16 + idx];
        g_bf[idx] = s;
    }
}

// full-width node precompute: P row (ull): [0..31]=sender pairs, [32..63]=receiver pairs
__global__ void k_node_pre(const float* __restrict__ V, const float* __restrict__ Wg, float* __restrict__ P) {
    extern __shared__ float sm[];
    float4* sW = (float4*)sm;           // 4096 float4 (64KB)
    float* sV = sm + 16384;             // 32*128 = 4096 floats (16KB)
    for (int i = threadIdx.x; i < 128 * 32; i += TPB) {
        int k = i >> 5, l = i & 31;
        sW[i] = make_float4(Wg[k * 64 + l], Wg[k * 64 + l + 32],
                            Wg[(128 + k) * 64 + l], Wg[(128 + k) * 64 + l + 32]);
    }
    __syncthreads();
    const ull* sWu = (const ull*)sW;
    const int warp = threadIdx.x >> 5, l = threadIdx.x & 31;
    const int ntiles = (BSZ * NN) / 32;
    for (int t = blockIdx.x; t < ntiles; t += gridDim.x) {
        __syncthreads();
        const float4* Vg = (const float4*)V + (size_t)t * 32 * 32;
        for (int i = threadIdx.x; i < 32 * 32; i += TPB) ((float4*)sV)[i] = __ldcs(Vg + i);
        __syncthreads();
        const int r0 = 4 * warp;
        ull a[4] = {0ULL, 0ULL, 0ULL, 0ULL}, bq[4] = {0ULL, 0ULL, 0ULL, 0ULL};
        const float4* sV4 = (const float4*)sV;
#pragma unroll 4
        for (int k4 = 0; k4 < 32; k4++) {
            ull wa[4], wb[4];
#pragma unroll
            for (int ki = 0; ki < 4; ki++) {
                int k = k4 * 4 + ki;
                wa[ki] = sWu[(k * 32 + l) * 2];
                wb[ki] = sWu[(k * 32 + l) * 2 + 1];
            }
#pragma unroll
            for (int r = 0; r < 4; r++) {
                float4 v = sV4[(r0 + r) * 32 + k4];
                a[r] = fma2(dup2(v.x), wa[0], a[r]); bq[r] = fma2(dup2(v.x), wb[0], bq[r]);
                a[r] = fma2(dup2(v.y), wa[1], a[r]); bq[r] = fma2(dup2(v.y), wb[1], bq[r]);
                a[r] = fma2(dup2(v.z), wa[2], a[r]); bq[r] = fma2(dup2(v.z), wb[2], bq[r]);
                a[r] = fma2(dup2(v.w), wa[3], a[r]); bq[r] = fma2(dup2(v.w), wb[3], bq[r]);
            }
        }
#pragma unroll
        for (int r = 0; r < 4; r++) {
            ull* p = (ull*)(P + ((size_t)t * 32 + r0 + r) * 128);
            p[l] = a[r]; p[32 + l] = bq[r];
        }
    }
}

// half-width precompute (for Pn): out[n] (32 ull) = V[n] @ W (128x64)
__global__ void __launch_bounds__(TPB, 4)
k_pre(const float* __restrict__ V, const float* __restrict__ W,
      float* __restrict__ P, int rowStrideUll, int colOffUll) {
    __shared__ ull sW[128 * 32];
    for (int i = threadIdx.x; i < 128 * 32; i += TPB) {
        int k = i >> 5, l = i & 31;
        sW[i] = pk2(W[k * 64 + l], W[k * 64 + l + 32]);
    }
    __syncthreads();
    const int warp = threadIdx.x >> 5, l = threadIdx.x & 31;
    const int nchunks = (BSZ * NN) / 8;
    for (int w = blockIdx.x * 8 + warp; w < nchunks; w += gridDim.x * 8) {
        const int r0 = w * 8;
        ull acc[8] = {0ULL, 0ULL, 0ULL, 0ULL, 0ULL, 0ULL, 0ULL, 0ULL};
        const float4* Vf = (const float4*)V + (size_t)r0 * 32;
#pragma unroll 4
        for (int k4 = 0; k4 < 32; k4++) {
            ull wk[4];
#pragma unroll
            for (int ki = 0; ki < 4; ki++) wk[ki] = sW[(k4 * 4 + ki) * 32 + l];
#pragma unroll
            for (int e = 0; e < 8; e++) {
                float4 v = __ldcs(Vf + e * 32 + k4);
                acc[e] = fma2(dup2(v.x), wk[0], acc[e]);
                acc[e] = fma2(dup2(v.y), wk[1], acc[e]);
                acc[e] = fma2(dup2(v.z), wk[2], acc[e]);
                acc[e] = fma2(dup2(v.w), wk[3], acc[e]);
            }
        }
        ull* Pu = (ull*)P;
#pragma unroll
        for (int e = 0; e < 8; e++)
            Pu[(size_t)(r0 + e) * rowStrideUll + colOffUll + l] = acc[e];
    }
}

// fused edge MLP, 8 edges/warp, warp-autonomous (NO block syncs in main loop).
// Per-warp smem quarter holds the warp's E tile, then reused for silu_h staging.
// smem floats: sW1 8192 | sW2 8192 | Wf 1024 | bf 16 | wa2 16 | sU 8192 = 25632 fl = 102528 B
template <bool MSG>
__global__ void __launch_bounds__(TPB, 2)
k_edge(const float* __restrict__ E, const int* __restrict__ edges,
       const float* __restrict__ W1, const float* __restrict__ b1,
       const float* __restrict__ W2, const float* __restrict__ b2,
       const float* __restrict__ Wa2, const float* __restrict__ ba2,
       const float* __restrict__ P, float* __restrict__ outE) {
    extern __shared__ float sm[];
    ull*    sW1u = (ull*)sm;
    float4* sW1f = (float4*)sm;
    float4* sW2f = (float4*)(sm + 8192);
    float4* sWfF = (float4*)(sm + 16384);
    float*  sBf  = sm + 17408;
    float*  sWa2s= sm + 17424;
    float*  sU   = sm + 17440;    // 8 warps * 1024 floats

    for (int i = threadIdx.x; i < 128 * 32; i += TPB) {
        int k = i >> 5, l = i & 31;
        sW1u[(k >> 1) * 64 + l * 2 + (k & 1)] =
            pk2(W1[(256 + k) * 64 + l], W1[(256 + k) * 64 + l + 32]);
    }
    for (int i = threadIdx.x; i < 64 * 32; i += TPB) {
        int j = i >> 5, l = i & 31;
        sW2f[i] = make_float4(W2[j * 128 + 4 * l], W2[j * 128 + 4 * l + 1],
                              W2[j * 128 + 4 * l + 2], W2[j * 128 + 4 * l + 3]);
    }
    if (MSG) {
        for (int i = threadIdx.x; i < 256; i += TPB) sWfF[i] = g_Wf4[i];
        if (threadIdx.x < 16) { sBf[threadIdx.x] = g_bf[threadIdx.x]; sWa2s[threadIdx.x] = __ldg(Wa2 + threadIdx.x); }
    }
    const int warp = threadIdx.x >> 5, l = threadIdx.x & 31;
    const ull bbu  = pk2(__ldg(b1 + l), __ldg(b1 + l + 32));
    const ull b2lo = pk2(__ldg(b2 + 4 * l), __ldg(b2 + 4 * l + 1));
    const ull b2hi = pk2(__ldg(b2 + 4 * l + 2), __ldg(b2 + 4 * l + 3));
    const float ba2v = MSG ? __ldg(ba2) : 0.f;
    __syncthreads();

    float* sQ = sU + warp * 1024;            // warp-private quarter
    const float4* sQ4 = (const float4*)sQ;
    float* sHw = sQ;                          // reused for silu_h (576 floats)
    const float4* E4 = (const float4*)E;
    const int nchunks = (BSZ * NEg) / 8;
    const int wstride = gridDim.x * 8;
    int w = blockIdx.x * 8 + warp;
    float4 ereg[8];
    if (w < nchunks) {
#pragma unroll
        for (int j = 0; j < 8; j++) ereg[j] = __ldcs(E4 + (size_t)w * 256 + j * 32 + l);
    }
    for (; w < nchunks; w += wstride) {
        // stage this chunk's E (registers -> own quarter); lane l holds k4=l of edge j
#pragma unroll
        for (int j = 0; j < 8; j++) ((float4*)sQ)[j * 32 + l] = ereg[j];
        __syncwarp();
        const int ge0 = w * 8;
        const int b = ge0 / NEg;
        int rx[8];
        ull sp[8], rp[8];
        const int2* edp = (const int2*)edges + ge0;
        const ull* Pu = (const ull*)P + (size_t)b * NN * 64;
#pragma unroll
        for (int e = 0; e < 8; e++) {
            int2 t2 = __ldg(edp + e);
            rx[e] = t2.y;
            sp[e] = __ldg(Pu + (size_t)t2.x * 64 + l);
            rp[e] = __ldg(Pu + (size_t)t2.y * 64 + 32 + l);
        }
        ull h[8];
#pragma unroll
        for (int e = 0; e < 8; e++) h[e] = bbu;
#pragma unroll 4
        for (int k4 = 0; k4 < 32; k4++) {
            float4 wa = sW1f[(2 * k4) * 32 + l];
            float4 wb = sW1f[(2 * k4 + 1) * 32 + l];
            ull w0 = pk2(wa.x, wa.y), w1 = pk2(wa.z, wa.w);
            ull w2_ = pk2(wb.x, wb.y), w3 = pk2(wb.z, wb.w);
#pragma unroll
            for (int e = 0; e < 8; e++) {
                float4 ev = sQ4[e * 32 + k4];
                h[e] = fma2(dup2(ev.x), w0, h[e]);
                h[e] = fma2(dup2(ev.y), w1, h[e]);
                h[e] = fma2(dup2(ev.z), w2_, h[e]);
                h[e] = fma2(dup2(ev.w), w3, h[e]);
            }
        }
        // prefetch next chunk's E while stage2/attention run
        {
            int wn = w + wstride;
            if (wn < nchunks) {
#pragma unroll
                for (int j = 0; j < 8; j++) ereg[j] = __ldcs(E4 + (size_t)wn * 256 + j * 32 + l);
            }
        }
        // consume deferred P gathers now (latency hidden behind GEMM)
#pragma unroll
        for (int e = 0; e < 8; e++) h[e] = add2(h[e], add2(sp[e], rp[e]));
        __syncwarp();
#pragma unroll
        for (int e = 0; e < 8; e++) {
            float2 hh = up2(h[e]);
            sHw[e * 72 + l] = silu_f(hh.x);
            sHw[e * 72 + l + 32] = silu_f(hh.y);
        }
        __syncwarp();
        float ex[8]; float exf = 0.f;
        if (MSG) {
            const int e_att = l & 7, jg = l >> 3;
            const float* shrow = sHw + e_att * 72;
            float p0 = 0.f, p1 = 0.f, p2 = 0.f, p3 = 0.f;
#pragma unroll 8
            for (int c = 0; c < 64; c++) {
                float shc = shrow[c];
                float4 wfv = sWfF[c * 4 + jg];
                p0 += shc * wfv.x; p1 += shc * wfv.y;
                p2 += shc * wfv.z; p3 += shc * wfv.w;
            }
            float s = silu_f(p0 + sBf[jg * 4 + 0]) * sWa2s[jg * 4 + 0]
                    + silu_f(p1 + sBf[jg * 4 + 1]) * sWa2s[jg * 4 + 1]
                    + silu_f(p2 + sBf[jg * 4 + 2]) * sWa2s[jg * 4 + 2]
                    + silu_f(p3 + sBf[jg * 4 + 3]) * sWa2s[jg * 4 + 3];
            s += __shfl_xor_sync(0xffffffffu, s, 8);
            s += __shfl_xor_sync(0xffffffffu, s, 16);
            float logit = fminf(30.f, fmaxf(-30.f, ba2v + s));
            exf = __expf(logit);
#pragma unroll
            for (int e = 0; e < 8; e++) ex[e] = __shfl_sync(0xffffffffu, exf, e);
        }
        ull ma[8], mb[8];
#pragma unroll
        for (int e = 0; e < 8; e++) { ma[e] = b2lo; mb[e] = b2hi; }
#pragma unroll 2
        for (int c4 = 0; c4 < 16; c4++) {
            float4 hh[8];
#pragma unroll
            for (int e = 0; e < 8; e++) hh[e] = *(const float4*)(sHw + e * 72 + 4 * c4);
#pragma unroll
            for (int ci = 0; ci < 4; ci++) {
                int c = 4 * c4 + ci;
                float4 wv = sW2f[c * 32 + l];
                ull wlo = pk2(wv.x, wv.y), whi = pk2(wv.z, wv.w);
#pragma unroll
                for (int e = 0; e < 8; e++) {
                    float hv = (ci == 0) ? hh[e].x : (ci == 1) ? hh[e].y : (ci == 2) ? hh[e].z : hh[e].w;
                    ull d = dup2(hv);
                    ma[e] = fma2(d, wlo, ma[e]);
                    mb[e] = fma2(d, whi, mb[e]);
                }
            }
        }
        if (MSG) {
#pragma unroll
            for (int e = 0; e < 8; e++) {
                ull exd = dup2(ex[e]);
                float2 MA = up2(mul2(ma[e], exd)), MB = up2(mul2(mb[e], exd));
                float* ap = g_agg + (size_t)(b * NN + rx[e]) * 128 + 4 * l;
                red4(ap, MA.x, MA.y, MB.x, MB.y);
            }
            if (l < 8) atomicAdd(&g_den[b * NN + rx[l]], 0.f);   // placeholder removed below
        } else {
#pragma unroll
            for (int e = 0; e < 8; e++) {
                float2 MA = up2(ma[e]), MB = up2(mb[e]);
                __stcs((float4*)outE + (size_t)(ge0 + e) * 32 + l,
                       make_float4(MA.x, MA.y, MB.x, MB.y));
            }
        }
        if (MSG && l < 8) {
            int2 t2 = __ldg(edp + l);
            atomicAdd(&g_den[b * NN + t2.y], exf);
        }
        __syncwarp();
    }
}

// node output MLP with Pn hoist; deferred den/Pn loads.
// smem floats: sW1 8192 + sW2 8192 + sH 4608 = 20992 fl = 83968 B -> 2 CTAs/SM.
__global__ void __launch_bounds__(TPB, 2)
k_nodeout(const float* __restrict__ Wb, const float* __restrict__ bn1,
          const float* __restrict__ Wn2, const float* __restrict__ bn2,
          float* __restrict__ outN) {
    extern __shared__ float sm[];
    ull*    sW1u = (ull*)sm;
    float4* sW1f = (float4*)sm;
    float4* sW2f = (float4*)(sm + 8192);
    float*  sH   = sm + 16384;
    for (int i = threadIdx.x; i < 128 * 32; i += TPB) {
        int k = i >> 5, l = i & 31;
        sW1u[(k >> 1) * 64 + l * 2 + (k & 1)] =
            pk2(Wb[k * 64 + l], Wb[k * 64 + l + 32]);
    }
    for (int i = threadIdx.x; i < 64 * 32; i += TPB) {
        int j = i >> 5, l = i & 31;
        sW2f[i] = make_float4(Wn2[j * 128 + 4 * l], Wn2[j * 128 + 4 * l + 1],
                              Wn2[j * 128 + 4 * l + 2], Wn2[j * 128 + 4 * l + 3]);
    }
    const int warp = threadIdx.x >> 5, l = threadIdx.x & 31;
    const ull bbu  = pk2(__ldg(bn1 + l), __ldg(bn1 + l + 32));
    const ull b2lo = pk2(__ldg(bn2 + 4 * l), __ldg(bn2 + 4 * l + 1));
    const ull b2hi = pk2(__ldg(bn2 + 4 * l + 2), __ldg(bn2 + 4 * l + 3));
    __syncthreads();

    float* sHw = sH + warp * 576;
    const ull* Pnu = (const ull*)g_Pn;
    const int nchunks = (BSZ * NN) / 8;
    for (int w = blockIdx.x * 8 + warp; w < nchunks; w += gridDim.x * 8) {
        const int r0 = w * 8;
        float den8[8];
        ull pn[8];
#pragma unroll
        for (int e = 0; e < 8; e++) {
            den8[e] = __ldg(g_den + r0 + e);
            pn[e] = __ldg(Pnu + (size_t)(r0 + e) * 32 + l);
        }
        ull h[8] = {0ULL, 0ULL, 0ULL, 0ULL, 0ULL, 0ULL, 0ULL, 0ULL};
        const float4* Af = (const float4*)g_agg + (size_t)r0 * 32;
#pragma unroll 4
        for (int k4 = 0; k4 < 32; k4++) {
            float4 wa = sW1f[(2 * k4) * 32 + l];
            float4 wb = sW1f[(2 * k4 + 1) * 32 + l];
            ull w0 = pk2(wa.x, wa.y), w1 = pk2(wa.z, wa.w);
            ull w2_ = pk2(wb.x, wb.y), w3 = pk2(wb.z, wb.w);
#pragma unroll
            for (int e = 0; e < 8; e++) {
                float4 ev = __ldcs(Af + e * 32 + k4);
                h[e] = fma2(dup2(ev.x), w0, h[e]);
                h[e] = fma2(dup2(ev.y), w1, h[e]);
                h[e] = fma2(dup2(ev.z), w2_, h[e]);
                h[e] = fma2(dup2(ev.w), w3, h[e]);
            }
        }
        __syncwarp();
#pragma unroll
        for (int e = 0; e < 8; e++) {
            float inv = den8[e] != 0.f ? 1.f / den8[e] : 0.f;
            ull base = add2(pn[e], bbu);
            float2 hh = up2(fma2(dup2(inv), h[e], base));
            sHw[e * 72 + l] = silu_f(hh.x);
            sHw[e * 72 + l + 32] = silu_f(hh.y);
        }
        __syncwarp();
        ull ma[8], mb[8];
#pragma unroll
        for (int e = 0; e < 8; e++) { ma[e] = b2lo; mb[e] = b2hi; }
#pragma unroll 2
        for (int c4 = 0; c4 < 16; c4++) {
            float4 hh[8];
#pragma unroll
            for (int e = 0; e < 8; e++) hh[e] = *(const float4*)(sHw + e * 72 + 4 * c4);
#pragma unroll
            for (int ci = 0; ci < 4; ci++) {
                int c = 4 * c4 + ci;
                float4 wv = sW2f[c * 32 + l];
                ull wlo = pk2(wv.x, wv.y), whi = pk2(wv.z, wv.w);
#pragma unroll
                for (int e = 0; e < 8; e++) {
                    float hv = (ci == 0) ? hh[e].x : (ci == 1) ? hh[e].y : (ci == 2) ? hh[e].z : hh[e].w;
                    ull d = dup2(hv);
                    ma[e] = fma2(d, wlo, ma[e]);
                    mb[e] = fma2(d, whi, mb[e]);
                }
            }
        }
#pragma unroll
        for (int e = 0; e < 8; e++) {
            float2 MA = up2(ma[e]), MB = up2(mb[e]);
            __stcs((float4*)outN + (size_t)(r0 + e) * 32 + l,
                   make_float4(MA.x, MA.y, MB.x, MB.y));
        }
        __syncwarp();
    }
}

extern "C" void kernel_launch(void* const* d_in, const int* in_sizes, int n_in,
                              void* d_out, int out_size) {
    const float* V = (const float*)d_in[0];
    const float* E = (const float*)d_in[1];
    const int* edges = (const int*)d_in[2];
    const float* Wm1 = (const float*)d_in[3];
    const float* bm1 = (const float*)d_in[4];
    const float* Wm2 = (const float*)d_in[5];
    const float* bm2 = (const float*)d_in[6];
    const float* Wa1 = (const float*)d_in[7];
    const float* ba1 = (const float*)d_in[8];
    const float* Wa2 = (const float*)d_in[9];
    const float* ba2 = (const float*)d_in[10];
    const float* Wu1 = (const float*)d_in[11];
    const float* bu1 = (const float*)d_in[12];
    const float* Wu2 = (const float*)d_in[13];
    const float* bu2 = (const float*)d_in[14];
    const float* Wn1 = (const float*)d_in[15];
    const float* bn1 = (const float*)d_in[16];
    const float* Wn2 = (const float*)d_in[17];
    const float* bn2 = (const float*)d_in[18];
    float* outN = (float*)d_out;
    float* outE = outN + (size_t)BSZ * NN * 128;

    float* Pmsg; cudaGetSymbolAddress((void**)&Pmsg, g_Pmsg);
    float* Pupd; cudaGetSymbolAddress((void**)&Pupd, g_Pupd);
    float* Pn;   cudaGetSymbolAddress((void**)&Pn, g_Pn);

    cudaFuncSetAttribute(k_node_pre, cudaFuncAttributeMaxDynamicSharedMemorySize, 81920);
    cudaFuncSetAttribute(k_edge<true>, cudaFuncAttributeMaxDynamicSharedMemorySize, 102528);
    cudaFuncSetAttribute(k_edge<false>, cudaFuncAttributeMaxDynamicSharedMemorySize, 102528);
    cudaFuncSetAttribute(k_nodeout, cudaFuncAttributeMaxDynamicSharedMemorySize, 83968);

    k_init<<<1184, TPB>>>();
    k_fuse<<<8, TPB>>>(Wm2, bm2, Wa1, ba1);
    k_node_pre<<<592, TPB, 81920>>>(V, Wm1, Pmsg);
    k_node_pre<<<592, TPB, 81920>>>(V, Wu1, Pupd);
    k_pre<<<592, TPB>>>(V, Wn1, Pn, 32, 0);
    k_edge<true><<<592, TPB, 102528>>>(E, edges, Wm1, bm1, Wm2, bm2, Wa2, ba2, Pmsg, nullptr);
    k_edge<false><<<592, TPB, 102528>>>(E, edges, Wu1, bu1, Wu2, bu2, nullptr, nullptr, Pupd, outE);
    k_nodeout<<<592, TPB, 83968>>>(Wn1 + 128 * 64, bn1, Wn2, bn2, outN);
}

// round 8
// speedup vs baseline: 1.7909x; 1.2044x over previous
#include <cuda_runtime.h>

typedef unsigned long long ull;
#define BSZ 2
#define NN 50000
#define NEg 400000
#define TPB 256

__device__ float g_Pmsg[BSZ * NN * 128];
__device__ float g_Pupd[BSZ * NN * 128];
__device__ float g_Pn[BSZ * NN * 64];
__device__ float g_agg[BSZ * NN * 64];    // aggregated ex*silu_h, pair layout: [2l]=dim l, [2l+1]=dim l+32
__device__ float g_den[BSZ * NN];
__device__ float4 g_Wf4[256];   // fused W2@Wa1 as [c][j], float4 over j
__device__ float g_bf[16];      // b2@Wa1 + ba1
__device__ ull   g_Wn64[64 * 32];  // fused W2m@Wn1_bot, indexed [storagePos p][lane l] -> (w[c(p)][l], w[c(p)][l+32])
__device__ ull   g_bn64[32];       // b2m@Wn1_bot pairs

__device__ __forceinline__ ull fma2(ull a, ull b, ull c) {
    ull d; asm("fma.rn.f32x2 %0, %1, %2, %3;" : "=l"(d) : "l"(a), "l"(b), "l"(c)); return d;
}
__device__ __forceinline__ ull add2(ull a, ull b) {
    ull d; asm("add.rn.f32x2 %0, %1, %2;" : "=l"(d) : "l"(a), "l"(b)); return d;
}
__device__ __forceinline__ ull pk2(float x, float y) {
    ull r; asm("mov.b64 %0, {%1, %2};" : "=l"(r) : "f"(x), "f"(y)); return r;
}
__device__ __forceinline__ ull dup2(float x) {
    ull r; asm("mov.b64 %0, {%1, %1};" : "=l"(r) : "f"(x)); return r;
}
__device__ __forceinline__ float2 up2(ull v) {
    float2 r; asm("mov.b64 {%0, %1}, %2;" : "=f"(r.x), "=f"(r.y) : "l"(v)); return r;
}
__device__ __forceinline__ float silu_f(float x) { return x / (1.f + __expf(-x)); }
__device__ __forceinline__ void red2(float* p, float a, float b) {
    asm volatile("red.global.add.v2.f32 [%0], {%1,%2};" :: "l"(p), "f"(a), "f"(b) : "memory");
}

__global__ void k_init() {
    float4 z = make_float4(0.f, 0.f, 0.f, 0.f);
    for (int i = blockIdx.x * blockDim.x + threadIdx.x; i < BSZ * NN * 16; i += gridDim.x * blockDim.x)
        ((float4*)g_agg)[i] = z;
    for (int i = blockIdx.x * blockDim.x + threadIdx.x; i < BSZ * NN; i += gridDim.x * blockDim.x)
        g_den[i] = 0.f;
}

// Wf[c][j] = sum_d W2[c][d]*Wa1[d][j];  bf[j] = b2@Wa1 + ba1
__global__ void k_fuse(const float* __restrict__ W2, const float* __restrict__ b2,
                       const float* __restrict__ Wa1, const float* __restrict__ ba1) {
    int idx = blockIdx.x * blockDim.x + threadIdx.x;
    if (idx < 1024) {
        int c = idx >> 4, j = idx & 15;
        float s = 0.f;
        for (int d = 0; d < 128; d++) s += W2[c * 128 + d] * Wa1[d * 16 + j];
        ((float*)g_Wf4)[c * 16 + j] = s;
    }
    if (idx < 16) {
        float s = ba1[idx];
        for (int d = 0; d < 128; d++) s += b2[d] * Wa1[d * 16 + idx];
        g_bf[idx] = s;
    }
}

// Wn64[p][l] = (sum_o W2m[c(p)][o]*Wn1bot[o][l], same for l+32); c(p) = p even ? p/2 : 32+p/2
__global__ void k_fuse2(const float* __restrict__ W2, const float* __restrict__ b2,
                        const float* __restrict__ Wn1bot) {
    int idx = blockIdx.x * blockDim.x + threadIdx.x;
    if (idx < 2048) {
        int p = idx >> 5, l = idx & 31;
        int c = (p & 1) ? 32 + (p >> 1) : (p >> 1);
        float s0 = 0.f, s1 = 0.f;
        for (int o = 0; o < 128; o++) {
            float w2v = W2[c * 128 + o];
            s0 += w2v * Wn1bot[o * 64 + l];
            s1 += w2v * Wn1bot[o * 64 + l + 32];
        }
        g_Wn64[p * 32 + l] = pk2(s0, s1);
    }
    if (idx < 32) {
        float s0 = 0.f, s1 = 0.f;
        for (int o = 0; o < 128; o++) {
            s0 += b2[o] * Wn1bot[o * 64 + idx];
            s1 += b2[o] * Wn1bot[o * 64 + idx + 32];
        }
        g_bn64[idx] = pk2(s0, s1);
    }
}

// full-width node precompute: P row (ull): [0..31]=sender pairs, [32..63]=receiver pairs
__global__ void k_node_pre(const float* __restrict__ V, const float* __restrict__ Wg, float* __restrict__ P) {
    extern __shared__ float sm[];
    float4* sW = (float4*)sm;
    float* sV = sm + 16384;
    for (int i = threadIdx.x; i < 128 * 32; i += TPB) {
        int k = i >> 5, l = i & 31;
        sW[i] = make_float4(Wg[k * 64 + l], Wg[k * 64 + l + 32],
                            Wg[(128 + k) * 64 + l], Wg[(128 + k) * 64 + l + 32]);
    }
    __syncthreads();
    const ull* sWu = (const ull*)sW;
    const int warp = threadIdx.x >> 5, l = threadIdx.x & 31;
    const int ntiles = (BSZ * NN) / 32;
    for (int t = blockIdx.x; t < ntiles; t += gridDim.x) {
        __syncthreads();
        const float4* Vg = (const float4*)V + (size_t)t * 32 * 32;
        for (int i = threadIdx.x; i < 32 * 32; i += TPB) ((float4*)sV)[i] = __ldcs(Vg + i);
        __syncthreads();
        const int r0 = 4 * warp;
        ull a[4] = {0ULL, 0ULL, 0ULL, 0ULL}, bq[4] = {0ULL, 0ULL, 0ULL, 0ULL};
        const float4* sV4 = (const float4*)sV;
#pragma unroll 4
        for (int k4 = 0; k4 < 32; k4++) {
            ull wa[4], wb[4];
#pragma unroll
            for (int ki = 0; ki < 4; ki++) {
                int k = k4 * 4 + ki;
                wa[ki] = sWu[(k * 32 + l) * 2];
                wb[ki] = sWu[(k * 32 + l) * 2 + 1];
            }
#pragma unroll
            for (int r = 0; r < 4; r++) {
                float4 v = sV4[(r0 + r) * 32 + k4];
                a[r] = fma2(dup2(v.x), wa[0], a[r]); bq[r] = fma2(dup2(v.x), wb[0], bq[r]);
                a[r] = fma2(dup2(v.y), wa[1], a[r]); bq[r] = fma2(dup2(v.y), wb[1], bq[r]);
                a[r] = fma2(dup2(v.z), wa[2], a[r]); bq[r] = fma2(dup2(v.z), wb[2], bq[r]);
                a[r] = fma2(dup2(v.w), wa[3], a[r]); bq[r] = fma2(dup2(v.w), wb[3], bq[r]);
            }
        }
#pragma unroll
        for (int r = 0; r < 4; r++) {
            ull* p = (ull*)(P + ((size_t)t * 32 + r0 + r) * 128);
            p[l] = a[r]; p[32 + l] = bq[r];
        }
    }
}

// half-width precompute (for Pn)
__global__ void __launch_bounds__(TPB, 4)
k_pre(const float* __restrict__ V, const float* __restrict__ W,
      float* __restrict__ P, int rowStrideUll, int colOffUll) {
    __shared__ ull sW[128 * 32];
    for (int i = threadIdx.x; i < 128 * 32; i += TPB) {
        int k = i >> 5, l = i & 31;
        sW[i] = pk2(W[k * 64 + l], W[k * 64 + l + 32]);
    }
    __syncthreads();
    const int warp = threadIdx.x >> 5, l = threadIdx.x & 31;
    const int nchunks = (BSZ * NN) / 8;
    for (int w = blockIdx.x * 8 + warp; w < nchunks; w += gridDim.x * 8) {
        const int r0 = w * 8;
        ull acc[8] = {0ULL, 0ULL, 0ULL, 0ULL, 0ULL, 0ULL, 0ULL, 0ULL};
        const float4* Vf = (const float4*)V + (size_t)r0 * 32;
#pragma unroll 4
        for (int k4 = 0; k4 < 32; k4++) {
            ull wk[4];
#pragma unroll
            for (int ki = 0; ki < 4; ki++) wk[ki] = sW[(k4 * 4 + ki) * 32 + l];
#pragma unroll
            for (int e = 0; e < 8; e++) {
                float4 v = __ldcs(Vf + e * 32 + k4);
                acc[e] = fma2(dup2(v.x), wk[0], acc[e]);
                acc[e] = fma2(dup2(v.y), wk[1], acc[e]);
                acc[e] = fma2(dup2(v.z), wk[2], acc[e]);
                acc[e] = fma2(dup2(v.w), wk[3], acc[e]);
            }
        }
        ull* Pu = (ull*)P;
#pragma unroll
        for (int e = 0; e < 8; e++)
            Pu[(size_t)(r0 + e) * rowStrideUll + colOffUll + l] = acc[e];
    }
}

// fused edge MLP, 8 edges/warp, warp-autonomous.
// MSG: stage1 + attention + red2 scatter of ex*silu_h (64-dim). NO stage2.
// UPD: stage1 + stage2 + store edge_delta.
template <bool MSG>
__global__ void __launch_bounds__(TPB, 2)
k_edge(const float* __restrict__ E, const int* __restrict__ edges,
       const float* __restrict__ W1, const float* __restrict__ b1,
       const float* __restrict__ W2, const float* __restrict__ b2,
       const float* __restrict__ Wa2, const float* __restrict__ ba2,
       const float* __restrict__ P, float* __restrict__ outE) {
    extern __shared__ float sm[];
    ull*    sW1u = (ull*)sm;
    float4* sW1f = (float4*)sm;
    float4* sW2f = (float4*)(sm + 8192);      // UPD only
    float4* sWfF = (float4*)(sm + 8192);      // MSG only
    float*  sBf  = sm + 9216;
    float*  sWa2s= sm + 9232;
    float*  sU   = sm + (MSG ? 9248 : 16384); // 8 warps * 1024 floats

    for (int i = threadIdx.x; i < 128 * 32; i += TPB) {
        int k = i >> 5, l = i & 31;
        sW1u[(k >> 1) * 64 + l * 2 + (k & 1)] =
            pk2(W1[(256 + k) * 64 + l], W1[(256 + k) * 64 + l + 32]);
    }
    if constexpr (!MSG) {
        for (int i = threadIdx.x; i < 64 * 32; i += TPB) {
            int j = i >> 5, l = i & 31;
            sW2f[i] = make_float4(W2[j * 128 + 4 * l], W2[j * 128 + 4 * l + 1],
                                  W2[j * 128 + 4 * l + 2], W2[j * 128 + 4 * l + 3]);
        }
    } else {
        for (int i = threadIdx.x; i < 256; i += TPB) sWfF[i] = g_Wf4[i];
        if (threadIdx.x < 16) { sBf[threadIdx.x] = g_bf[threadIdx.x]; sWa2s[threadIdx.x] = __ldg(Wa2 + threadIdx.x); }
    }
    const int warp = threadIdx.x >> 5, l = threadIdx.x & 31;
    const ull bbu  = pk2(__ldg(b1 + l), __ldg(b1 + l + 32));
    ull b2lo = 0ULL, b2hi = 0ULL;
    if constexpr (!MSG) {
        b2lo = pk2(__ldg(b2 + 4 * l), __ldg(b2 + 4 * l + 1));
        b2hi = pk2(__ldg(b2 + 4 * l + 2), __ldg(b2 + 4 * l + 3));
    }
    const float ba2v = MSG ? __ldg(ba2) : 0.f;
    __syncthreads();

    float* sQ = sU + warp * 1024;
    const float4* sQ4 = (const float4*)sQ;
    float* sHw = sQ;
    const float4* E4 = (const float4*)E;
    const int nchunks = (BSZ * NEg) / 8;
    const int wstride = gridDim.x * 8;
    int w = blockIdx.x * 8 + warp;
    float4 ereg[8];
    if (w < nchunks) {
#pragma unroll
        for (int j = 0; j < 8; j++) ereg[j] = __ldcs(E4 + (size_t)w * 256 + j * 32 + l);
    }
    for (; w < nchunks; w += wstride) {
#pragma unroll
        for (int j = 0; j < 8; j++) ((float4*)sQ)[j * 32 + l] = ereg[j];
        __syncwarp();
        const int ge0 = w * 8;
        const int b = ge0 / NEg;
        int rx[8];
        ull sp[8], rp[8];
        const int2* edp = (const int2*)edges + ge0;
        const ull* Pu = (const ull*)P + (size_t)b * NN * 64;
#pragma unroll
        for (int e = 0; e < 8; e++) {
            int2 t2 = __ldg(edp + e);
            rx[e] = t2.y;
            sp[e] = __ldg(Pu + (size_t)t2.x * 64 + l);
            rp[e] = __ldg(Pu + (size_t)t2.y * 64 + 32 + l);
        }
        ull h[8];
#pragma unroll
        for (int e = 0; e < 8; e++) h[e] = bbu;
#pragma unroll 4
        for (int k4 = 0; k4 < 32; k4++) {
            float4 wa = sW1f[(2 * k4) * 32 + l];
            float4 wb = sW1f[(2 * k4 + 1) * 32 + l];
            ull w0 = pk2(wa.x, wa.y), w1 = pk2(wa.z, wa.w);
            ull w2_ = pk2(wb.x, wb.y), w3 = pk2(wb.z, wb.w);
#pragma unroll
            for (int e = 0; e < 8; e++) {
                float4 ev = sQ4[e * 32 + k4];
                h[e] = fma2(dup2(ev.x), w0, h[e]);
                h[e] = fma2(dup2(ev.y), w1, h[e]);
                h[e] = fma2(dup2(ev.z), w2_, h[e]);
                h[e] = fma2(dup2(ev.w), w3, h[e]);
            }
        }
        {
            int wn = w + wstride;
            if (wn < nchunks) {
#pragma unroll
                for (int j = 0; j < 8; j++) ereg[j] = __ldcs(E4 + (size_t)wn * 256 + j * 32 + l);
            }
        }
#pragma unroll
        for (int e = 0; e < 8; e++) h[e] = add2(h[e], add2(sp[e], rp[e]));
        __syncwarp();
        float2 SH[8];
#pragma unroll
        for (int e = 0; e < 8; e++) {
            float2 hh = up2(h[e]);
            SH[e].x = silu_f(hh.x); SH[e].y = silu_f(hh.y);
            sHw[e * 72 + l] = SH[e].x;
            sHw[e * 72 + l + 32] = SH[e].y;
        }
        __syncwarp();
        if constexpr (MSG) {
            const int e_att = l & 7, jg = l >> 3;
            const float* shrow = sHw + e_att * 72;
            float p0 = 0.f, p1 = 0.f, p2 = 0.f, p3 = 0.f;
#pragma unroll 8
            for (int c = 0; c < 64; c++) {
                float shc = shrow[c];
                float4 wfv = sWfF[c * 4 + jg];
                p0 += shc * wfv.x; p1 += shc * wfv.y;
                p2 += shc * wfv.z; p3 += shc * wfv.w;
            }
            float s = silu_f(p0 + sBf[jg * 4 + 0]) * sWa2s[jg * 4 + 0]
                    + silu_f(p1 + sBf[jg * 4 + 1]) * sWa2s[jg * 4 + 1]
                    + silu_f(p2 + sBf[jg * 4 + 2]) * sWa2s[jg * 4 + 2]
                    + silu_f(p3 + sBf[jg * 4 + 3]) * sWa2s[jg * 4 + 3];
            s += __shfl_xor_sync(0xffffffffu, s, 8);
            s += __shfl_xor_sync(0xffffffffu, s, 16);
            float logit = fminf(30.f, fmaxf(-30.f, ba2v + s));
            float exf = __expf(logit);
            float ex[8];
#pragma unroll
            for (int e = 0; e < 8; e++) ex[e] = __shfl_sync(0xffffffffu, exf, e);
            // scatter ex * silu_h (64-dim, pair layout)
#pragma unroll
            for (int e = 0; e < 8; e++) {
                float* ap = g_agg + (size_t)(b * NN + rx[e]) * 64 + 2 * l;
                red2(ap, ex[e] * SH[e].x, ex[e] * SH[e].y);
            }
            if (l < 8) atomicAdd(&g_den[b * NN + rx[l]], exf);
        } else {
            ull ma[8], mb[8];
#pragma unroll
            for (int e = 0; e < 8; e++) { ma[e] = b2lo; mb[e] = b2hi; }
#pragma unroll 2
            for (int c4 = 0; c4 < 16; c4++) {
                float4 hh[8];
#pragma unroll
                for (int e = 0; e < 8; e++) hh[e] = *(const float4*)(sHw + e * 72 + 4 * c4);
#pragma unroll
                for (int ci = 0; ci < 4; ci++) {
                    int c = 4 * c4 + ci;
                    float4 wv = sW2f[c * 32 + l];
                    ull wlo = pk2(wv.x, wv.y), whi = pk2(wv.z, wv.w);
#pragma unroll
                    for (int e = 0; e < 8; e++) {
                        float hv = (ci == 0) ? hh[e].x : (ci == 1) ? hh[e].y : (ci == 2) ? hh[e].z : hh[e].w;
                        ull d = dup2(hv);
                        ma[e] = fma2(d, wlo, ma[e]);
                        mb[e] = fma2(d, whi, mb[e]);
                    }
                }
            }
#pragma unroll
            for (int e = 0; e < 8; e++) {
                float2 MA = up2(ma[e]), MB = up2(mb[e]);
                __stcs((float4*)outE + (size_t)(ge0 + e) * 32 + l,
                       make_float4(MA.x, MA.y, MB.x, MB.y));
            }
        }
        __syncwarp();
    }
}

// node output MLP: h = Pn + bn1 + sel*badd + inv*(Hagg @ Wn64); silu; @ Wn2 + bn2
// smem floats: sW1 4096 + sW2 8192 + sH 4608 = 16896 fl = 67584 B
__global__ void __launch_bounds__(TPB, 2)
k_nodeout(const float* __restrict__ bn1, const float* __restrict__ Wn2,
          const float* __restrict__ bn2, float* __restrict__ outN) {
    extern __shared__ float sm[];
    ull*    sW1u = (ull*)sm;                  // 2048 ull
    float4* sW2f = (float4*)(sm + 4096);
    float*  sH   = sm + 12288;
    for (int i = threadIdx.x; i < 64 * 32; i += TPB) sW1u[i] = g_Wn64[i];
    for (int i = threadIdx.x; i < 64 * 32; i += TPB) {
        int j = i >> 5, l = i & 31;
        sW2f[i] = make_float4(Wn2[j * 128 + 4 * l], Wn2[j * 128 + 4 * l + 1],
                              Wn2[j * 128 + 4 * l + 2], Wn2[j * 128 + 4 * l + 3]);
    }
    const int warp = threadIdx.x >> 5, l = threadIdx.x & 31;
    const ull bbu   = pk2(__ldg(bn1 + l), __ldg(bn1 + l + 32));
    const ull baddu = g_bn64[l];
    const ull b2lo = pk2(__ldg(bn2 + 4 * l), __ldg(bn2 + 4 * l + 1));
    const ull b2hi = pk2(__ldg(bn2 + 4 * l + 2), __ldg(bn2 + 4 * l + 3));
    __syncthreads();

    float* sHw = sH + warp * 576;
    const ull* Pnu = (const ull*)g_Pn;
    const int nchunks = (BSZ * NN) / 8;
    for (int w = blockIdx.x * 8 + warp; w < nchunks; w += gridDim.x * 8) {
        const int r0 = w * 8;
        float den8[8];
        ull pn[8];
#pragma unroll
        for (int e = 0; e < 8; e++) {
            den8[e] = __ldg(g_den + r0 + e);
            pn[e] = __ldg(Pnu + (size_t)(r0 + e) * 32 + l);
        }
        ull h[8] = {0ULL, 0ULL, 0ULL, 0ULL, 0ULL, 0ULL, 0ULL, 0ULL};
        const float4* Af = (const float4*)g_agg + (size_t)r0 * 16;
#pragma unroll 4
        for (int k4 = 0; k4 < 16; k4++) {
            ull wk[4];
#pragma unroll
            for (int ki = 0; ki < 4; ki++) wk[ki] = sW1u[(k4 * 4 + ki) * 32 + l];
#pragma unroll
            for (int e = 0; e < 8; e++) {
                float4 v = __ldcs(Af + e * 16 + k4);
                h[e] = fma2(dup2(v.x), wk[0], h[e]);
                h[e] = fma2(dup2(v.y), wk[1], h[e]);
                h[e] = fma2(dup2(v.z), wk[2], h[e]);
                h[e] = fma2(dup2(v.w), wk[3], h[e]);
            }
        }
        __syncwarp();
#pragma unroll
        for (int e = 0; e < 8; e++) {
            float nz = den8[e] != 0.f ? 1.f : 0.f;
            float inv = den8[e] != 0.f ? 1.f / den8[e] : 0.f;
            ull base = add2(pn[e], bbu);
            base = fma2(dup2(nz), baddu, base);
            float2 hh = up2(fma2(dup2(inv), h[e], base));
            sHw[e * 72 + l] = silu_f(hh.x);
            sHw[e * 72 + l + 32] = silu_f(hh.y);
        }
        __syncwarp();
        ull ma[8], mb[8];
#pragma unroll
        for (int e = 0; e < 8; e++) { ma[e] = b2lo; mb[e] = b2hi; }
#pragma unroll 2
        for (int c4 = 0; c4 < 16; c4++) {
            float4 hh[8];
#pragma unroll
            for (int e = 0; e < 8; e++) hh[e] = *(const float4*)(sHw + e * 72 + 4 * c4);
#pragma unroll
            for (int ci = 0; ci < 4; ci++) {
                int c = 4 * c4 + ci;
                float4 wv = sW2f[c * 32 + l];
                ull wlo = pk2(wv.x, wv.y), whi = pk2(wv.z, wv.w);
#pragma unroll
                for (int e = 0; e < 8; e++) {
                    float hv = (ci == 0) ? hh[e].x : (ci == 1) ? hh[e].y : (ci == 2) ? hh[e].z : hh[e].w;
                    ull d = dup2(hv);
                    ma[e] = fma2(d, wlo, ma[e]);
                    mb[e] = fma2(d, whi, mb[e]);
                }
            }
        }
#pragma unroll
        for (int e = 0; e < 8; e++) {
            float2 MA = up2(ma[e]), MB = up2(mb[e]);
            __stcs((float4*)outN + (size_t)(r0 + e) * 32 + l,
                   make_float4(MA.x, MA.y, MB.x, MB.y));
        }
        __syncwarp();
    }
}

extern "C" void kernel_launch(void* const* d_in, const int* in_sizes, int n_in,
                              void* d_out, int out_size) {
    const float* V = (const float*)d_in[0];
    const float* E = (const float*)d_in[1];
    const int* edges = (const int*)d_in[2];
    const float* Wm1 = (const float*)d_in[3];
    const float* bm1 = (const float*)d_in[4];
    const float* Wm2 = (const float*)d_in[5];
    const float* bm2 = (const float*)d_in[6];
    const float* Wa1 = (const float*)d_in[7];
    const float* ba1 = (const float*)d_in[8];
    const float* Wa2 = (const float*)d_in[9];
    const float* ba2 = (const float*)d_in[10];
    const float* Wu1 = (const float*)d_in[11];
    const float* bu1 = (const float*)d_in[12];
    const float* Wu2 = (const float*)d_in[13];
    const float* bu2 = (const float*)d_in[14];
    const float* Wn1 = (const float*)d_in[15];
    const float* bn1 = (const float*)d_in[16];
    const float* Wn2 = (const float*)d_in[17];
    const float* bn2 = (const float*)d_in[18];
    float* outN = (float*)d_out;
    float* outE = outN + (size_t)BSZ * NN * 128;

    float* Pmsg; cudaGetSymbolAddress((void**)&Pmsg, g_Pmsg);
    float* Pupd; cudaGetSymbolAddress((void**)&Pupd, g_Pupd);
    float* Pn;   cudaGetSymbolAddress((void**)&Pn, g_Pn);

    cudaFuncSetAttribute(k_node_pre, cudaFuncAttributeMaxDynamicSharedMemorySize, 81920);
    cudaFuncSetAttribute(k_edge<true>, cudaFuncAttributeMaxDynamicSharedMemorySize, 69760);
    cudaFuncSetAttribute(k_edge<false>, cudaFuncAttributeMaxDynamicSharedMemorySize, 98304);
    cudaFuncSetAttribute(k_nodeout, cudaFuncAttributeMaxDynamicSharedMemorySize, 67584);

    k_init<<<592, TPB>>>();
    k_fuse<<<8, TPB>>>(Wm2, bm2, Wa1, ba1);
    k_fuse2<<<8, TPB>>>(Wm2, bm2, Wn1 + 128 * 64);
    k_node_pre<<<592, TPB, 81920>>>(V, Wm1, Pmsg);
    k_node_pre<<<592, TPB, 81920>>>(V, Wu1, Pupd);
    k_pre<<<592, TPB>>>(V, Wn1, Pn, 32, 0);
    k_edge<true><<<592, TPB, 69760>>>(E, edges, Wm1, bm1, Wm2, bm2, Wa2, ba2, Pmsg, nullptr);
    k_edge<false><<<592, TPB, 98304>>>(E, edges, Wu1, bu1, Wu2, bu2, nullptr, nullptr, Pupd, outE);
    k_nodeout<<<592, TPB, 67584>>>(bn1, Wn2, bn2, outN);
}

// round 9
// speedup vs baseline: 1.9866x; 1.1093x over previous
#include <cuda_runtime.h>

typedef unsigned long long ull;
#define BSZ 2
#define NN 50000
#define NEg 400000

__device__ float g_P[BSZ * NN * 256];     // combined msg/upd projections, interleaved (see k_npre2)
__device__ float g_Pn[BSZ * NN * 64];
__device__ float g_agg[BSZ * NN * 64];    // aggregated ex*silu_h, pair layout: [2l]=dim l, [2l+1]=dim l+32
__device__ float g_den[BSZ * NN];
__device__ float4 g_Wf4[256];   // fused W2@Wa1 as [c][j], float4 over j
__device__ float g_bf[16];      // b2@Wa1 + ba1
__device__ ull   g_Wn64[64 * 32];  // fused W2m@Wn1_bot
__device__ ull   g_bn64[32];       // b2m@Wn1_bot pairs

__device__ __forceinline__ ull fma2(ull a, ull b, ull c) {
    ull d; asm("fma.rn.f32x2 %0, %1, %2, %3;" : "=l"(d) : "l"(a), "l"(b), "l"(c)); return d;
}
__device__ __forceinline__ ull add2(ull a, ull b) {
    ull d; asm("add.rn.f32x2 %0, %1, %2;" : "=l"(d) : "l"(a), "l"(b)); return d;
}
__device__ __forceinline__ ull pk2(float x, float y) {
    ull r; asm("mov.b64 %0, {%1, %2};" : "=l"(r) : "f"(x), "f"(y)); return r;
}
__device__ __forceinline__ ull dup2(float x) {
    ull r; asm("mov.b64 %0, {%1, %1};" : "=l"(r) : "f"(x)); return r;
}
__device__ __forceinline__ float2 up2(ull v) {
    float2 r; asm("mov.b64 {%0, %1}, %2;" : "=f"(r.x), "=f"(r.y) : "l"(v)); return r;
}
__device__ __forceinline__ float silu_f(float x) { return x / (1.f + __expf(-x)); }
__device__ __forceinline__ void red2(float* p, float a, float b) {
    asm volatile("red.global.add.v2.f32 [%0], {%1,%2};" :: "l"(p), "f"(a), "f"(b) : "memory");
}

__global__ void k_init() {
    float4 z = make_float4(0.f, 0.f, 0.f, 0.f);
    for (int i = blockIdx.x * blockDim.x + threadIdx.x; i < BSZ * NN * 16; i += gridDim.x * blockDim.x)
        ((float4*)g_agg)[i] = z;
    for (int i = blockIdx.x * blockDim.x + threadIdx.x; i < BSZ * NN; i += gridDim.x * blockDim.x)
        g_den[i] = 0.f;
}

// Wf[c][j] = sum_d W2[c][d]*Wa1[d][j];  bf[j] = b2@Wa1 + ba1
__global__ void k_fuse(const float* __restrict__ W2, const float* __restrict__ b2,
                       const float* __restrict__ Wa1, const float* __restrict__ ba1) {
    int idx = blockIdx.x * blockDim.x + threadIdx.x;
    if (idx < 1024) {
        int c = idx >> 4, j = idx & 15;
        float s = 0.f;
        for (int d = 0; d < 128; d++) s += W2[c * 128 + d] * Wa1[d * 16 + j];
        ((float*)g_Wf4)[c * 16 + j] = s;
    }
    if (idx < 16) {
        float s = ba1[idx];
        for (int d = 0; d < 128; d++) s += b2[d] * Wa1[d * 16 + idx];
        g_bf[idx] = s;
    }
}

// Wn64[p][l] = (sum_o W2m[c(p)][o]*Wn1bot[o][l], l+32); c(p) = p even ? p/2 : 32+p/2
__global__ void k_fuse2(const float* __restrict__ W2, const float* __restrict__ b2,
                        const float* __restrict__ Wn1bot) {
    int idx = blockIdx.x * blockDim.x + threadIdx.x;
    if (idx < 2048) {
        int p = idx >> 5, l = idx & 31;
        int c = (p & 1) ? 32 + (p >> 1) : (p >> 1);
        float s0 = 0.f, s1 = 0.f;
        for (int o = 0; o < 128; o++) {
            float w2v = W2[c * 128 + o];
            s0 += w2v * Wn1bot[o * 64 + l];
            s1 += w2v * Wn1bot[o * 64 + l + 32];
        }
        g_Wn64[p * 32 + l] = pk2(s0, s1);
    }
    if (idx < 32) {
        float s0 = 0.f, s1 = 0.f;
        for (int o = 0; o < 128; o++) {
            s0 += b2[o] * Wn1bot[o * 64 + idx];
            s1 += b2[o] * Wn1bot[o * 64 + idx + 32];
        }
        g_bn64[idx] = pk2(s0, s1);
    }
}

// Fused node precompute (msg + upd), 5 rows/warp, warp-autonomous.
// P row layout (ulonglong2 units, stride 64):
//  [row*64 + l]      = (msg_sender_pair_l, upd_sender_pair_l)
//  [row*64 + 32 + l] = (msg_recv_pair_l,   upd_recv_pair_l)
__global__ void __launch_bounds__(512, 1)
k_npre2(const float* __restrict__ V, const float* __restrict__ Wm1,
        const float* __restrict__ Wu1, float* __restrict__ P) {
    extern __shared__ float sm[];
    ull* sWm = (ull*)sm;              // 8192 ull: sender block [0..4096), recv block [4096..8192)
    ull* sWu = sWm + 8192;            // 8192 ull
    float* sV = sm + 32768;           // 16 warps * 640 floats

    for (int i = threadIdx.x; i < 128 * 32; i += 512) {
        int k = i >> 5, l = i & 31;
        int pos = (k >> 1) * 64 + l * 2 + (k & 1);
        sWm[pos]        = pk2(Wm1[k * 64 + l],         Wm1[k * 64 + l + 32]);
        sWm[4096 + pos] = pk2(Wm1[(128 + k) * 64 + l], Wm1[(128 + k) * 64 + l + 32]);
        sWu[pos]        = pk2(Wu1[k * 64 + l],         Wu1[k * 64 + l + 32]);
        sWu[4096 + pos] = pk2(Wu1[(128 + k) * 64 + l], Wu1[(128 + k) * 64 + l + 32]);
    }
    __syncthreads();
    const int warp = threadIdx.x >> 5, l = threadIdx.x & 31;
    const float4* fmsS = (const float4*)sWm;
    const float4* fmsR = fmsS + 2048;
    const float4* fupS = (const float4*)sWu;
    const float4* fupR = fupS + 2048;
    float* sVq = sV + warp * 640;
    float4* sVq4 = (float4*)sVq;
    const float4* V4 = (const float4*)V;
    ulonglong2* P2 = (ulonglong2*)P;

    const int nchunks = (BSZ * NN) / 5;   // 20000
    const int wstride = gridDim.x * 16;
    for (int w = blockIdx.x * 16 + warp; w < nchunks; w += wstride) {
        const int r0 = w * 5;
        __syncwarp();
#pragma unroll
        for (int r = 0; r < 5; r++) sVq4[r * 32 + l] = __ldcs(V4 + (size_t)(r0 + r) * 32 + l);
        __syncwarp();
        ull am[5], bmq[5], au[5], buq[5];
#pragma unroll
        for (int r = 0; r < 5; r++) { am[r] = 0ULL; bmq[r] = 0ULL; au[r] = 0ULL; buq[r] = 0ULL; }
#pragma unroll 4
        for (int k4 = 0; k4 < 32; k4++) {
            float4 mS0 = fmsS[(2 * k4) * 32 + l], mS1 = fmsS[(2 * k4 + 1) * 32 + l];
            float4 mR0 = fmsR[(2 * k4) * 32 + l], mR1 = fmsR[(2 * k4 + 1) * 32 + l];
            float4 uS0 = fupS[(2 * k4) * 32 + l], uS1 = fupS[(2 * k4 + 1) * 32 + l];
            float4 uR0 = fupR[(2 * k4) * 32 + l], uR1 = fupR[(2 * k4 + 1) * 32 + l];
            ull wmS[4] = {pk2(mS0.x, mS0.y), pk2(mS0.z, mS0.w), pk2(mS1.x, mS1.y), pk2(mS1.z, mS1.w)};
            ull wmR[4] = {pk2(mR0.x, mR0.y), pk2(mR0.z, mR0.w), pk2(mR1.x, mR1.y), pk2(mR1.z, mR1.w)};
            ull wuS[4] = {pk2(uS0.x, uS0.y), pk2(uS0.z, uS0.w), pk2(uS1.x, uS1.y), pk2(uS1.z, uS1.w)};
            ull wuR[4] = {pk2(uR0.x, uR0.y), pk2(uR0.z, uR0.w), pk2(uR1.x, uR1.y), pk2(uR1.z, uR1.w)};
#pragma unroll
            for (int r = 0; r < 5; r++) {
                float4 v = sVq4[r * 32 + k4];
                am[r]  = fma2(dup2(v.x), wmS[0], am[r]);  am[r]  = fma2(dup2(v.y), wmS[1], am[r]);
                am[r]  = fma2(dup2(v.z), wmS[2], am[r]);  am[r]  = fma2(dup2(v.w), wmS[3], am[r]);
                bmq[r] = fma2(dup2(v.x), wmR[0], bmq[r]); bmq[r] = fma2(dup2(v.y), wmR[1], bmq[r]);
                bmq[r] = fma2(dup2(v.z), wmR[2], bmq[r]); bmq[r] = fma2(dup2(v.w), wmR[3], bmq[r]);
                au[r]  = fma2(dup2(v.x), wuS[0], au[r]);  au[r]  = fma2(dup2(v.y), wuS[1], au[r]);
                au[r]  = fma2(dup2(v.z), wuS[2], au[r]);  au[r]  = fma2(dup2(v.w), wuS[3], au[r]);
                buq[r] = fma2(dup2(v.x), wuR[0], buq[r]); buq[r] = fma2(dup2(v.y), wuR[1], buq[r]);
                buq[r] = fma2(dup2(v.z), wuR[2], buq[r]); buq[r] = fma2(dup2(v.w), wuR[3], buq[r]);
            }
        }
#pragma unroll
        for (int r = 0; r < 5; r++) {
            size_t row = r0 + r;
            P2[row * 64 + l]      = make_ulonglong2(am[r], au[r]);
            P2[row * 64 + 32 + l] = make_ulonglong2(bmq[r], buq[r]);
        }
    }
}

// half-width precompute (for Pn)
__global__ void __launch_bounds__(256, 4)
k_pre(const float* __restrict__ V, const float* __restrict__ W, float* __restrict__ P) {
    __shared__ ull sW[128 * 32];
    for (int i = threadIdx.x; i < 128 * 32; i += 256) {
        int k = i >> 5, l = i & 31;
        sW[i] = pk2(W[k * 64 + l], W[k * 64 + l + 32]);
    }
    __syncthreads();
    const int warp = threadIdx.x >> 5, l = threadIdx.x & 31;
    const int nchunks = (BSZ * NN) / 8;
    for (int w = blockIdx.x * 8 + warp; w < nchunks; w += gridDim.x * 8) {
        const int r0 = w * 8;
        ull acc[8] = {0ULL, 0ULL, 0ULL, 0ULL, 0ULL, 0ULL, 0ULL, 0ULL};
        const float4* Vf = (const float4*)V + (size_t)r0 * 32;
#pragma unroll 4
        for (int k4 = 0; k4 < 32; k4++) {
            ull wk[4];
#pragma unroll
            for (int ki = 0; ki < 4; ki++) wk[ki] = sW[(k4 * 4 + ki) * 32 + l];
#pragma unroll
            for (int e = 0; e < 8; e++) {
                float4 v = __ldcs(Vf + e * 32 + k4);
                acc[e] = fma2(dup2(v.x), wk[0], acc[e]);
                acc[e] = fma2(dup2(v.y), wk[1], acc[e]);
                acc[e] = fma2(dup2(v.z), wk[2], acc[e]);
                acc[e] = fma2(dup2(v.w), wk[3], acc[e]);
            }
        }
        ull* Pu = (ull*)P;
#pragma unroll
        for (int e = 0; e < 8; e++) Pu[(size_t)(r0 + e) * 32 + l] = acc[e];
    }
}

// Fused edge kernel: MSG (stage1 + attention + scatter) and UPD (stage1 + stage2 + edge_delta)
// in one pass. 8 edges/warp, warp-autonomous. E staged once; P gathered as ull2.
__global__ void __launch_bounds__(512, 1)
k_edge_fused(const float* __restrict__ E, const int* __restrict__ edges,
             const float* __restrict__ Wm1, const float* __restrict__ bm1,
             const float* __restrict__ Wu1, const float* __restrict__ bu1,
             const float* __restrict__ Wu2, const float* __restrict__ bu2,
             const float* __restrict__ Wa2, const float* __restrict__ ba2,
             const float* __restrict__ P, float* __restrict__ outE) {
    extern __shared__ float sm[];
    ull*    sWm  = (ull*)sm;                 // 4096 ull (floats 0..8192)
    float4* sWmf = (float4*)sm;
    ull*    sWu  = (ull*)(sm + 8192);        // 4096 ull
    float4* sWuf = (float4*)(sm + 8192);
    float4* sW2f = (float4*)(sm + 16384);    // 2048 float4
    float4* sWfF = (float4*)(sm + 24576);    // 256 float4
    float*  sBf  = sm + 25600;
    float*  sWa2s= sm + 25616;
    float*  sU   = sm + 25632;               // 16 warps * 1024 floats

    for (int i = threadIdx.x; i < 128 * 32; i += 512) {
        int k = i >> 5, l = i & 31;
        int pos = (k >> 1) * 64 + l * 2 + (k & 1);
        sWm[pos] = pk2(Wm1[(256 + k) * 64 + l], Wm1[(256 + k) * 64 + l + 32]);
        sWu[pos] = pk2(Wu1[(256 + k) * 64 + l], Wu1[(256 + k) * 64 + l + 32]);
    }
    for (int i = threadIdx.x; i < 64 * 32; i += 512) {
        int j = i >> 5, l = i & 31;
        sW2f[i] = make_float4(Wu2[j * 128 + 4 * l], Wu2[j * 128 + 4 * l + 1],
                              Wu2[j * 128 + 4 * l + 2], Wu2[j * 128 + 4 * l + 3]);
    }
    for (int i = threadIdx.x; i < 256; i += 512) sWfF[i] = g_Wf4[i];
    if (threadIdx.x < 16) { sBf[threadIdx.x] = g_bf[threadIdx.x]; sWa2s[threadIdx.x] = __ldg(Wa2 + threadIdx.x); }
    const int warp = threadIdx.x >> 5, l = threadIdx.x & 31;
    const ull bbm  = pk2(__ldg(bm1 + l), __ldg(bm1 + l + 32));
    const ull bbuu = pk2(__ldg(bu1 + l), __ldg(bu1 + l + 32));
    const ull b2lo = pk2(__ldg(bu2 + 4 * l), __ldg(bu2 + 4 * l + 1));
    const ull b2hi = pk2(__ldg(bu2 + 4 * l + 2), __ldg(bu2 + 4 * l + 3));
    const float ba2v = __ldg(ba2);
    __syncthreads();

    float* sQ = sU + warp * 1024;
    const float4* sQ4 = (const float4*)sQ;
    float* sHw = sQ;   // reused after both stage-1 GEMMs
    const float4* E4 = (const float4*)E;
    const int nchunks = (BSZ * NEg) / 8;       // 100000
    const int wstride = gridDim.x * 16;
    int w = blockIdx.x * 16 + warp;
    float4 ereg[8];
    if (w < nchunks) {
#pragma unroll
        for (int j = 0; j < 8; j++) ereg[j] = __ldcs(E4 + (size_t)w * 256 + j * 32 + l);
    }
    for (; w < nchunks; w += wstride) {
        __syncwarp();
#pragma unroll
        for (int j = 0; j < 8; j++) ((float4*)sQ)[j * 32 + l] = ereg[j];
        __syncwarp();
        const int ge0 = w * 8;
        const int b = ge0 / NEg;
        int rx[8];
        ull hm[8], hu[8];
        const int2* edp = (const int2*)edges + ge0;
        const ulonglong2* Pu2 = (const ulonglong2*)P + (size_t)b * NN * 64;
#pragma unroll
        for (int e = 0; e < 8; e++) {
            int2 t2 = __ldg(edp + e);
            rx[e] = t2.y;
            ulonglong2 s2 = __ldg(Pu2 + (size_t)t2.x * 64 + l);
            ulonglong2 r2 = __ldg(Pu2 + (size_t)t2.y * 64 + 32 + l);
            hm[e] = add2(add2(s2.x, r2.x), bbm);
            hu[e] = add2(add2(s2.y, r2.y), bbuu);
        }
        // stage1 UPD
#pragma unroll 4
        for (int k4 = 0; k4 < 32; k4++) {
            float4 wa = sWuf[(2 * k4) * 32 + l];
            float4 wb = sWuf[(2 * k4 + 1) * 32 + l];
            ull w0 = pk2(wa.x, wa.y), w1 = pk2(wa.z, wa.w);
            ull w2_ = pk2(wb.x, wb.y), w3 = pk2(wb.z, wb.w);
#pragma unroll
            for (int e = 0; e < 8; e++) {
                float4 ev = sQ4[e * 32 + k4];
                hu[e] = fma2(dup2(ev.x), w0, hu[e]);
                hu[e] = fma2(dup2(ev.y), w1, hu[e]);
                hu[e] = fma2(dup2(ev.z), w2_, hu[e]);
                hu[e] = fma2(dup2(ev.w), w3, hu[e]);
            }
        }
        // stage1 MSG
#pragma unroll 4
        for (int k4 = 0; k4 < 32; k4++) {
            float4 wa = sWmf[(2 * k4) * 32 + l];
            float4 wb = sWmf[(2 * k4 + 1) * 32 + l];
            ull w0 = pk2(wa.x, wa.y), w1 = pk2(wa.z, wa.w);
            ull w2_ = pk2(wb.x, wb.y), w3 = pk2(wb.z, wb.w);
#pragma unroll
            for (int e = 0; e < 8; e++) {
                float4 ev = sQ4[e * 32 + k4];
                hm[e] = fma2(dup2(ev.x), w0, hm[e]);
                hm[e] = fma2(dup2(ev.y), w1, hm[e]);
                hm[e] = fma2(dup2(ev.z), w2_, hm[e]);
                hm[e] = fma2(dup2(ev.w), w3, hm[e]);
            }
        }
        // prefetch next chunk's E (sQ about to be repurposed)
        {
            int wn = w + wstride;
            if (wn < nchunks) {
#pragma unroll
                for (int j = 0; j < 8; j++) ereg[j] = __ldcs(E4 + (size_t)wn * 256 + j * 32 + l);
            }
        }
        __syncwarp();
        // MSG: silu -> sHw, attention, scatter
        float2 SH[8];
#pragma unroll
        for (int e = 0; e < 8; e++) {
            float2 hh = up2(hm[e]);
            SH[e].x = silu_f(hh.x); SH[e].y = silu_f(hh.y);
            sHw[e * 72 + l] = SH[e].x;
            sHw[e * 72 + l + 32] = SH[e].y;
        }
        __syncwarp();
        {
            const int e_att = l & 7, jg = l >> 3;
            const float* shrow = sHw + e_att * 72;
            float p0 = 0.f, p1 = 0.f, p2 = 0.f, p3 = 0.f;
#pragma unroll 8
            for (int c = 0; c < 64; c++) {
                float shc = shrow[c];
                float4 wfv = sWfF[c * 4 + jg];
                p0 += shc * wfv.x; p1 += shc * wfv.y;
                p2 += shc * wfv.z; p3 += shc * wfv.w;
            }
            float s = silu_f(p0 + sBf[jg * 4 + 0]) * sWa2s[jg * 4 + 0]
                    + silu_f(p1 + sBf[jg * 4 + 1]) * sWa2s[jg * 4 + 1]
                    + silu_f(p2 + sBf[jg * 4 + 2]) * sWa2s[jg * 4 + 2]
                    + silu_f(p3 + sBf[jg * 4 + 3]) * sWa2s[jg * 4 + 3];
            s += __shfl_xor_sync(0xffffffffu, s, 8);
            s += __shfl_xor_sync(0xffffffffu, s, 16);
            float logit = fminf(30.f, fmaxf(-30.f, ba2v + s));
            float exf = __expf(logit);
            float ex[8];
#pragma unroll
            for (int e = 0; e < 8; e++) ex[e] = __shfl_sync(0xffffffffu, exf, e);
#pragma unroll
            for (int e = 0; e < 8; e++) {
                float* ap = g_agg + (size_t)(b * NN + rx[e]) * 64 + 2 * l;
                red2(ap, ex[e] * SH[e].x, ex[e] * SH[e].y);
            }
            if (l < 8) {
                int2 t2 = __ldg(edp + l);
                atomicAdd(&g_den[b * NN + t2.y], exf);
            }
        }
        // UPD: silu -> sHw (overwrite), stage2, store edge_delta
        __syncwarp();
#pragma unroll
        for (int e = 0; e < 8; e++) {
            float2 hh = up2(hu[e]);
            sHw[e * 72 + l] = silu_f(hh.x);
            sHw[e * 72 + l + 32] = silu_f(hh.y);
        }
        __syncwarp();
        ull ma[8], mb[8];
#pragma unroll
        for (int e = 0; e < 8; e++) { ma[e] = b2lo; mb[e] = b2hi; }
#pragma unroll 2
        for (int c4 = 0; c4 < 16; c4++) {
            float4 hh[8];
#pragma unroll
            for (int e = 0; e < 8; e++) hh[e] = *(const float4*)(sHw + e * 72 + 4 * c4);
#pragma unroll
            for (int ci = 0; ci < 4; ci++) {
                int c = 4 * c4 + ci;
                float4 wv = sW2f[c * 32 + l];
                ull wlo = pk2(wv.x, wv.y), whi = pk2(wv.z, wv.w);
#pragma unroll
                for (int e = 0; e < 8; e++) {
                    float hv = (ci == 0) ? hh[e].x : (ci == 1) ? hh[e].y : (ci == 2) ? hh[e].z : hh[e].w;
                    ull d = dup2(hv);
                    ma[e] = fma2(d, wlo, ma[e]);
                    mb[e] = fma2(d, whi, mb[e]);
                }
            }
        }
#pragma unroll
        for (int e = 0; e < 8; e++) {
            float2 MA = up2(ma[e]), MB = up2(mb[e]);
            __stcs((float4*)outE + (size_t)(ge0 + e) * 32 + l,
                   make_float4(MA.x, MA.y, MB.x, MB.y));
        }
    }
}

// node output MLP: h = Pn + bn1 + sel*badd + inv*(Hagg @ Wn64); silu; @ Wn2 + bn2
__global__ void __launch_bounds__(256, 2)
k_nodeout(const float* __restrict__ bn1, const float* __restrict__ Wn2,
          const float* __restrict__ bn2, float* __restrict__ outN) {
    extern __shared__ float sm[];
    ull*    sW1u = (ull*)sm;                  // 2048 ull
    float4* sW2f = (float4*)(sm + 4096);
    float*  sH   = sm + 12288;
    for (int i = threadIdx.x; i < 64 * 32; i += 256) sW1u[i] = g_Wn64[i];
    for (int i = threadIdx.x; i < 64 * 32; i += 256) {
        int j = i >> 5, l = i & 31;
        sW2f[i] = make_float4(Wn2[j * 128 + 4 * l], Wn2[j * 128 + 4 * l + 1],
                              Wn2[j * 128 + 4 * l + 2], Wn2[j * 128 + 4 * l + 3]);
    }
    const int warp = threadIdx.x >> 5, l = threadIdx.x & 31;
    const ull bbu   = pk2(__ldg(bn1 + l), __ldg(bn1 + l + 32));
    const ull baddu = g_bn64[l];
    const ull b2lo = pk2(__ldg(bn2 + 4 * l), __ldg(bn2 + 4 * l + 1));
    const ull b2hi = pk2(__ldg(bn2 + 4 * l + 2), __ldg(bn2 + 4 * l + 3));
    __syncthreads();

    float* sHw = sH + warp * 576;
    const ull* Pnu = (const ull*)g_Pn;
    const int nchunks = (BSZ * NN) / 8;
    for (int w = blockIdx.x * 8 + warp; w < nchunks; w += gridDim.x * 8) {
        const int r0 = w * 8;
        float den8[8];
        ull pn[8];
#pragma unroll
        for (int e = 0; e < 8; e++) {
            den8[e] = __ldg(g_den + r0 + e);
            pn[e] = __ldg(Pnu + (size_t)(r0 + e) * 32 + l);
        }
        ull h[8] = {0ULL, 0ULL, 0ULL, 0ULL, 0ULL, 0ULL, 0ULL, 0ULL};
        const float4* Af = (const float4*)g_agg + (size_t)r0 * 16;
#pragma unroll 4
        for (int k4 = 0; k4 < 16; k4++) {
            ull wk[4];
#pragma unroll
            for (int ki = 0; ki < 4; ki++) wk[ki] = sW1u[(k4 * 4 + ki) * 32 + l];
#pragma unroll
            for (int e = 0; e < 8; e++) {
                float4 v = __ldcs(Af + e * 16 + k4);
                h[e] = fma2(dup2(v.x), wk[0], h[e]);
                h[e] = fma2(dup2(v.y), wk[1], h[e]);
                h[e] = fma2(dup2(v.z), wk[2], h[e]);
                h[e] = fma2(dup2(v.w), wk[3], h[e]);
            }
        }
        __syncwarp();
#pragma unroll
        for (int e = 0; e < 8; e++) {
            float nz = den8[e] != 0.f ? 1.f : 0.f;
            float inv = den8[e] != 0.f ? 1.f / den8[e] : 0.f;
            ull base = add2(pn[e], bbu);
            base = fma2(dup2(nz), baddu, base);
            float2 hh = up2(fma2(dup2(inv), h[e], base));
            sHw[e * 72 + l] = silu_f(hh.x);
            sHw[e * 72 + l + 32] = silu_f(hh.y);
        }
        __syncwarp();
        ull ma[8], mb[8];
#pragma unroll
        for (int e = 0; e < 8; e++) { ma[e] = b2lo; mb[e] = b2hi; }
#pragma unroll 2
        for (int c4 = 0; c4 < 16; c4++) {
            float4 hh[8];
#pragma unroll
            for (int e = 0; e < 8; e++) hh[e] = *(const float4*)(sHw + e * 72 + 4 * c4);
#pragma unroll
            for (int ci = 0; ci < 4; ci++) {
                int c = 4 * c4 + ci;
                float4 wv = sW2f[c * 32 + l];
                ull wlo = pk2(wv.x, wv.y), whi = pk2(wv.z, wv.w);
#pragma unroll
                for (int e = 0; e < 8; e++) {
                    float hv = (ci == 0) ? hh[e].x : (ci == 1) ? hh[e].y : (ci == 2) ? hh[e].z : hh[e].w;
                    ull d = dup2(hv);
                    ma[e] = fma2(d, wlo, ma[e]);
                    mb[e] = fma2(d, whi, mb[e]);
                }
            }
        }
#pragma unroll
        for (int e = 0; e < 8; e++) {
            float2 MA = up2(ma[e]), MB = up2(mb[e]);
            __stcs((float4*)outN + (size_t)(r0 + e) * 32 + l,
                   make_float4(MA.x, MA.y, MB.x, MB.y));
        }
        __syncwarp();
    }
}

extern "C" void kernel_launch(void* const* d_in, const int* in_sizes, int n_in,
                              void* d_out, int out_size) {
    const float* V = (const float*)d_in[0];
    const float* E = (const float*)d_in[1];
    const int* edges = (const int*)d_in[2];
    const float* Wm1 = (const float*)d_in[3];
    const float* bm1 = (const float*)d_in[4];
    const float* Wm2 = (const float*)d_in[5];
    const float* bm2 = (const float*)d_in[6];
    const float* Wa1 = (const float*)d_in[7];
    const float* ba1 = (const float*)d_in[8];
    const float* Wa2 = (const float*)d_in[9];
    const float* ba2 = (const float*)d_in[10];
    const float* Wu1 = (const float*)d_in[11];
    const float* bu1 = (const float*)d_in[12];
    const float* Wu2 = (const float*)d_in[13];
    const float* bu2 = (const float*)d_in[14];
    const float* Wn1 = (const float*)d_in[15];
    const float* bn1 = (const float*)d_in[16];
    const float* Wn2 = (const float*)d_in[17];
    const float* bn2 = (const float*)d_in[18];
    float* outN = (float*)d_out;
    float* outE = outN + (size_t)BSZ * NN * 128;

    float* Pc; cudaGetSymbolAddress((void**)&Pc, g_P);
    float* Pn; cudaGetSymbolAddress((void**)&Pn, g_Pn);

    cudaFuncSetAttribute(k_npre2, cudaFuncAttributeMaxDynamicSharedMemorySize, 172032);
    cudaFuncSetAttribute(k_edge_fused, cudaFuncAttributeMaxDynamicSharedMemorySize, 168064);
    cudaFuncSetAttribute(k_nodeout, cudaFuncAttributeMaxDynamicSharedMemorySize, 67584);

    k_init<<<592, 256>>>();
    k_fuse<<<8, 256>>>(Wm2, bm2, Wa1, ba1);
    k_fuse2<<<8, 256>>>(Wm2, bm2, Wn1 + 128 * 64);
    k_npre2<<<148, 512, 172032>>>(V, Wm1, Wu1, Pc);
    k_pre<<<592, 256>>>(V, Wn1, Pn);
    k_edge_fused<<<148, 512, 168064>>>(E, edges, Wm1, bm1, Wu1, bu1, Wu2, bu2, Wa2, ba2, Pc, outE);
    k_nodeout<<<592, 256, 67584>>>(bn1, Wn2, bn2, outN);
}